// round 1
// baseline (speedup 1.0000x reference)
#include <cuda_runtime.h>
#include <cuda_bf16.h>
#include <math.h>

// Problem dims (fixed by the reference)
#define B_    4
#define N_    2048
#define D_    1024
#define H_    16
#define HD_   64
#define S_    11
#define M_    (B_ * N_)   // 8192

#define D4_0 0.4829629131445341f
#define D4_1 0.8365163037378079f
#define D4_2 0.2241438680420134f
#define D4_3 (-0.1294095225512604f)

// ---------------- scratch (static device globals; no allocation) -------------
__device__ float g_qkv [M_ * 3 * D_];        // [8192, 3072]
__device__ float g_gate[M_ * D_];            // sigmoid(x@Wg^T + bg)
__device__ float g_field[B_ * H_ * N_ * HD_];
__device__ float g_gains[B_ * H_ * N_ * S_];
__device__ float g_outf [B_ * H_ * N_ * HD_];
__device__ float g_G    [M_ * D_];           // gathered * gate

// ---------------- SGEMM: C[M,Nc] = A[M,K] @ W[Nc,K]^T + bias, opt sigmoid ----
#define BM 128
#define BN 128
#define BK 8
#define TM 8
#define TN 8

__global__ __launch_bounds__(256)
void sgemm_bias_kernel(const float* __restrict__ A, const float* __restrict__ W,
                       const float* __restrict__ bias, float* __restrict__ C,
                       int M, int Nc, int K, int sigmoidFlag)
{
    __shared__ float As[BK][BM];
    __shared__ float Bs[BK][BN];

    const int tid = threadIdx.x;
    const int bx = blockIdx.x;   // Nc tile
    const int by = blockIdx.y;   // M tile

    const float* Ablk = A + (size_t)by * BM * K;
    const float* Wblk = W + (size_t)bx * BN * K;

    const int lrow = tid >> 1;          // 0..127
    const int lcol = (tid & 1) * 4;     // 0 or 4

    const int ty = tid >> 4;            // 0..15
    const int tx = tid & 15;            // 0..15

    float acc[TM][TN];
#pragma unroll
    for (int i = 0; i < TM; i++)
#pragma unroll
        for (int j = 0; j < TN; j++) acc[i][j] = 0.f;

    for (int k0 = 0; k0 < K; k0 += BK) {
        float4 av = *(const float4*)(Ablk + (size_t)lrow * K + k0 + lcol);
        float4 bv = *(const float4*)(Wblk + (size_t)lrow * K + k0 + lcol);
        As[lcol + 0][lrow] = av.x; As[lcol + 1][lrow] = av.y;
        As[lcol + 2][lrow] = av.z; As[lcol + 3][lrow] = av.w;
        Bs[lcol + 0][lrow] = bv.x; Bs[lcol + 1][lrow] = bv.y;
        Bs[lcol + 2][lrow] = bv.z; Bs[lcol + 3][lrow] = bv.w;
        __syncthreads();

#pragma unroll
        for (int kk = 0; kk < BK; kk++) {
            float ar[TM], br[TN];
            *(float4*)(ar + 0) = *(const float4*)(&As[kk][ty * TM + 0]);
            *(float4*)(ar + 4) = *(const float4*)(&As[kk][ty * TM + 4]);
            *(float4*)(br + 0) = *(const float4*)(&Bs[kk][tx * TN + 0]);
            *(float4*)(br + 4) = *(const float4*)(&Bs[kk][tx * TN + 4]);
#pragma unroll
            for (int i = 0; i < TM; i++)
#pragma unroll
                for (int j = 0; j < TN; j++)
                    acc[i][j] = fmaf(ar[i], br[j], acc[i][j]);
        }
        __syncthreads();
    }

    float bvals[TN];
#pragma unroll
    for (int j = 0; j < TN; j++) bvals[j] = bias[bx * BN + tx * TN + j];

#pragma unroll
    for (int i = 0; i < TM; i++) {
        const int m = by * BM + ty * TM + i;
        float* crow = C + (size_t)m * Nc + bx * BN + tx * TN;
        float out[TN];
#pragma unroll
        for (int j = 0; j < TN; j++) {
            float c = acc[i][j] + bvals[j];
            if (sigmoidFlag) c = 1.f / (1.f + __expf(-c));
            out[j] = c;
        }
        *(float4*)(crow + 0) = *(const float4*)(out + 0);
        *(float4*)(crow + 4) = *(const float4*)(out + 4);
    }
}

// -------- stage: per-position gains (softmax over S) + field = v * ||k|| -----
// one warp per (b,h,n); lane t handles hd = t and t+32
__global__ __launch_bounds__(256)
void gains_field_kernel(const float* __restrict__ qkv,
                        const float* __restrict__ Wqs,
                        const float* __restrict__ scale_gain)
{
    const int warpsPerBlock = blockDim.x >> 5;
    const int wid = blockIdx.x * warpsPerBlock + (threadIdx.x >> 5);
    if (wid >= B_ * H_ * N_) return;
    const int lane = threadIdx.x & 31;

    const int n  = wid & (N_ - 1);
    const int bh = wid >> 11;            // N_ = 2048 = 2^11
    const int h  = bh & (H_ - 1);
    const int b  = bh >> 4;

    const float* base = qkv + (size_t)(b * N_ + n) * (3 * D_) + h * HD_;
    const float q0 = base[lane],            q1 = base[lane + 32];
    const float k0 = base[D_ + lane],       k1 = base[D_ + lane + 32];
    const float v0 = base[2 * D_ + lane],   v1 = base[2 * D_ + lane + 32];

    float ks = k0 * k0 + k1 * k1;
#pragma unroll
    for (int o = 16; o > 0; o >>= 1) ks += __shfl_xor_sync(0xffffffffu, ks, o);
    const float kmag = sqrtf(ks);

    const size_t fbase = ((size_t)bh * N_ + n) * HD_;
    g_field[fbase + lane]      = v0 * kmag;
    g_field[fbase + lane + 32] = v1 * kmag;

    float logit[S_];
#pragma unroll
    for (int s = 0; s < S_; s++) {
        float p = q0 * __ldg(&Wqs[s * HD_ + lane]) + q1 * __ldg(&Wqs[s * HD_ + lane + 32]);
#pragma unroll
        for (int o = 16; o > 0; o >>= 1) p += __shfl_xor_sync(0xffffffffu, p, o);
        logit[s] = p + __ldg(&scale_gain[s * H_ + h]);
    }
    float mx = logit[0];
#pragma unroll
    for (int s = 1; s < S_; s++) mx = fmaxf(mx, logit[s]);
    float e[S_], sum = 0.f;
#pragma unroll
    for (int s = 0; s < S_; s++) { e[s] = __expf(logit[s] - mx); sum += e[s]; }
    const float inv = 1.f / sum;

    const size_t gbase = (size_t)wid * S_;
#pragma unroll
    for (int s = 0; s < S_; s++)
        if (lane == s) g_gains[gbase + s] = e[s] * inv;
}

// -------- stage: causal multiscale dilated D4 conv, gain-weighted ------------
// block = 256 threads = 4 n-positions x 64 hd
__global__ __launch_bounds__(256)
void conv_kernel()
{
    const int bh = blockIdx.y;
    const int n  = blockIdx.x * 4 + (threadIdx.x >> 6);
    const int hd = threadIdx.x & 63;

    const float* fbase = g_field + (size_t)bh * N_ * HD_;
    const size_t gidx = ((size_t)bh * N_ + n) * S_;

    float g[S_];
#pragma unroll
    for (int s = 0; s < S_; s++) g[s] = __ldg(&g_gains[gidx + s]);

    // softmax gains sum to 1 -> offset-0 tap collapses
    float acc = D4_3 * fbase[(size_t)n * HD_ + hd];

#pragma unroll
    for (int j = 0; j < S_; j++) {
        const int d = 1 << j;
        const int s3 = n - 3 * d, s2 = n - 2 * d, s1 = n - d;
        if (s3 >= 0) acc = fmaf(g[j] * D4_0, fbase[(size_t)s3 * HD_ + hd], acc);
        if (s2 >= 0) acc = fmaf(g[j] * D4_1, fbase[(size_t)s2 * HD_ + hd], acc);
        if (s1 >= 0) acc = fmaf(g[j] * D4_2, fbase[(size_t)s1 * HD_ + hd], acc);
    }
    g_outf[((size_t)bh * N_ + n) * HD_ + hd] = acc;
}

// -------- stage: head coupling (softmax rows of 16x16) + gate multiply -------
// one block per (b,n); 256 threads handle 16 heads x 64 hd = 1024 outputs
__global__ __launch_bounds__(256)
void couple_gate_kernel(const float* __restrict__ fc)
{
    __shared__ float sf[H_ * HD_];       // 16 x 64
    __shared__ float cp[H_][H_];

    const int bn = blockIdx.x;
    const int b  = bn >> 11;
    const int n  = bn & (N_ - 1);
    const int tid = threadIdx.x;

#pragma unroll
    for (int r = 0; r < 4; r++) {
        const int idx = tid + r * 256;
        const int j = idx >> 6, hd = idx & 63;
        sf[idx] = g_outf[(((size_t)(b * H_ + j)) * N_ + n) * HD_ + hd];
    }
    if (tid < H_) {
        float row[H_];
        float mx = -1e30f;
#pragma unroll
        for (int j = 0; j < H_; j++) { row[j] = fc[tid * H_ + j]; mx = fmaxf(mx, row[j]); }
        float sum = 0.f;
#pragma unroll
        for (int j = 0; j < H_; j++) { row[j] = __expf(row[j] - mx); sum += row[j]; }
        const float inv = 1.f / sum;
#pragma unroll
        for (int j = 0; j < H_; j++) cp[tid][j] = row[j] * inv;
    }
    __syncthreads();

    const size_t grow = ((size_t)b * N_ + n) * D_;
#pragma unroll
    for (int r = 0; r < 4; r++) {
        const int idx = tid + r * 256;
        const int i = idx >> 6, hd = idx & 63;
        float acc = 0.f;
#pragma unroll
        for (int j = 0; j < H_; j++) acc = fmaf(cp[i][j], sf[j * HD_ + hd], acc);
        g_G[grow + idx] = acc * g_gate[grow + idx];
    }
}

// ------------------------------- launch --------------------------------------
extern "C" void kernel_launch(void* const* d_in, const int* in_sizes, int n_in,
                              void* d_out, int out_size)
{
    const float* x    = (const float*)d_in[0];   // [4,2048,1024]
    const float* Wqkv = (const float*)d_in[1];   // [3072,1024]
    const float* bqkv = (const float*)d_in[2];   // [3072]
    const float* Wo   = (const float*)d_in[3];   // [1024,1024]
    const float* bo   = (const float*)d_in[4];   // [1024]
    const float* Wg   = (const float*)d_in[5];   // [1024,1024]
    const float* bg   = (const float*)d_in[6];   // [1024]
    const float* scale_gain = (const float*)d_in[7]; // [11,16]
    const float* Wqs  = (const float*)d_in[8];   // [11,64]
    const float* fc   = (const float*)d_in[9];   // [16,16]
    float* out = (float*)d_out;

    float *p_qkv, *p_gate, *p_G;
    cudaGetSymbolAddress((void**)&p_qkv,  g_qkv);
    cudaGetSymbolAddress((void**)&p_gate, g_gate);
    cudaGetSymbolAddress((void**)&p_G,    g_G);

    // 1) qkv = x @ Wqkv^T + bqkv
    {
        dim3 grid(3 * D_ / BN, M_ / BM);
        sgemm_bias_kernel<<<grid, 256>>>(x, Wqkv, bqkv, p_qkv, M_, 3 * D_, D_, 0);
    }
    // 2) gate = sigmoid(x @ Wg^T + bg)
    {
        dim3 grid(D_ / BN, M_ / BM);
        sgemm_bias_kernel<<<grid, 256>>>(x, Wg, bg, p_gate, M_, D_, D_, 1);
    }
    // 3) gains + field
    {
        const int totalWarps = B_ * H_ * N_;       // 131072
        const int wpb = 8;
        gains_field_kernel<<<totalWarps / wpb, wpb * 32>>>(p_qkv, Wqs, scale_gain);
    }
    // 4) multiscale causal conv
    {
        dim3 grid(N_ / 4, B_ * H_);
        conv_kernel<<<grid, 256>>>();
    }
    // 5) head coupling + gate
    couple_gate_kernel<<<B_ * N_, 256>>>(fc);

    // 6) out = G @ Wo^T + bo
    {
        dim3 grid(D_ / BN, M_ / BM);
        sgemm_bias_kernel<<<grid, 256>>>(p_G, Wo, bo, out, M_, D_, D_, 0);
    }
}

// round 3
// speedup vs baseline: 2.2446x; 2.2446x over previous
#include <cuda_runtime.h>
#include <cuda_bf16.h>
#include <math.h>
#include <stdint.h>

// Problem dims (fixed by the reference)
#define B_    4
#define N_    2048
#define D_    1024
#define H_    16
#define HD_   64
#define S_    11
#define M_    (B_ * N_)   // 8192

#define D4_0 0.4829629131445341f
#define D4_1 0.8365163037378079f
#define D4_2 0.2241438680420134f
#define D4_3 (-0.1294095225512604f)

// ---------------- scratch (static device globals; no allocation) -------------
__device__ __align__(256) float g_qkv [M_ * 3 * D_];
__device__ __align__(256) float g_gate[M_ * D_];
__device__ __align__(256) float g_field[B_ * H_ * N_ * HD_];
__device__ __align__(256) float g_gains[B_ * H_ * N_ * S_];
__device__ __align__(256) float g_outf [B_ * H_ * N_ * HD_];

__device__ __align__(256) __nv_bfloat16 g_xhi[M_ * D_];
__device__ __align__(256) __nv_bfloat16 g_xlo[M_ * D_];
__device__ __align__(256) __nv_bfloat16 g_Ghi[M_ * D_];
__device__ __align__(256) __nv_bfloat16 g_Glo[M_ * D_];
__device__ __align__(256) __nv_bfloat16 g_Wqkvhi[3 * D_ * D_];
__device__ __align__(256) __nv_bfloat16 g_Wqkvlo[3 * D_ * D_];
__device__ __align__(256) __nv_bfloat16 g_Wghi[D_ * D_];
__device__ __align__(256) __nv_bfloat16 g_Wglo[D_ * D_];
__device__ __align__(256) __nv_bfloat16 g_Wohi[D_ * D_];
__device__ __align__(256) __nv_bfloat16 g_Wolo[D_ * D_];

// ============================ PTX helpers ====================================
__device__ __forceinline__ uint32_t smem_u32(const void* p) {
    uint32_t a;
    asm("{ .reg .u64 t; cvta.to.shared.u64 t, %1; cvt.u32.u64 %0, t; }" : "=r"(a) : "l"(p));
    return a;
}

#define CP_ASYNC_16(sp, gp) \
    asm volatile("cp.async.cg.shared.global [%0], [%1], 16;" :: "r"(sp), "l"(gp) : "memory")
#define CP_COMMIT() asm volatile("cp.async.commit_group;" ::: "memory")
#define CP_WAIT(n)  asm volatile("cp.async.wait_group %0;" :: "n"(n) : "memory")

#define LDSM4(r0, r1, r2, r3, addr) \
    asm volatile("ldmatrix.sync.aligned.m8n8.x4.shared.b16 {%0,%1,%2,%3}, [%4];" \
        : "=r"(r0), "=r"(r1), "=r"(r2), "=r"(r3) : "r"(addr))
#define LDSM2(r0, r1, addr) \
    asm volatile("ldmatrix.sync.aligned.m8n8.x2.shared.b16 {%0,%1}, [%2];" \
        : "=r"(r0), "=r"(r1) : "r"(addr))

#define MMA16816(d, a, b) \
    asm volatile("mma.sync.aligned.m16n8k16.row.col.f32.bf16.bf16.f32 " \
        "{%0,%1,%2,%3}, {%4,%5,%6,%7}, {%8,%9}, {%0,%1,%2,%3};" \
        : "+f"((d)[0]), "+f"((d)[1]), "+f"((d)[2]), "+f"((d)[3]) \
        : "r"((a)[0]), "r"((a)[1]), "r"((a)[2]), "r"((a)[3]), "r"((b)[0]), "r"((b)[1]))

// ======================= bf16x3 tensor-core GEMM =============================
// C[M, Nc] = A[M, K] @ W[Nc, K]^T + bias   via   Ahi*Bhi + Ahi*Blo + Alo*Bhi
#define GBM 128
#define GBN 128
#define GBK 32
#define NSTAGE 4
#define ROWB   80                   // 64B data + 16B pad (conflict-free ldmatrix)
#define TILEB  (128 * ROWB)         // 10240 B per operand tile
#define STAGEB (4 * TILEB)          // Ahi, Alo, Bhi, Blo = 40960 B per stage
#define GEMM_SMEM (NSTAGE * STAGEB) // 163840 B

__device__ __forceinline__ void load_stage(
    uint32_t sbase, int stage,
    const __nv_bfloat16* __restrict__ Ahi, const __nv_bfloat16* __restrict__ Alo,
    const __nv_bfloat16* __restrict__ Bhi, const __nv_bfloat16* __restrict__ Blo,
    int m0, int n0, int K, int kk, int t)
{
    const int r = ((0) << 6) + (t >> 2);   // base row for even j
    const int c = t & 3;
    const uint32_t sb = sbase + stage * STAGEB;
#pragma unroll
    for (int j = 0; j < 8; j++) {
        const int tile = j >> 1;
        const int row  = ((j & 1) << 6) + r;
        const __nv_bfloat16* g;
        int grow;
        if      (tile == 0) { g = Ahi; grow = m0 + row; }
        else if (tile == 1) { g = Alo; grow = m0 + row; }
        else if (tile == 2) { g = Bhi; grow = n0 + row; }
        else                { g = Blo; grow = n0 + row; }
        const __nv_bfloat16* gp = g + (size_t)grow * K + kk + c * 8;
        const uint32_t sp = sb + tile * TILEB + row * ROWB + c * 16;
        CP_ASYNC_16(sp, gp);
    }
    CP_COMMIT();
}

__global__ __launch_bounds__(256, 1)
void gemm_bf16x3(const __nv_bfloat16* __restrict__ Ahi, const __nv_bfloat16* __restrict__ Alo,
                 const __nv_bfloat16* __restrict__ Bhi, const __nv_bfloat16* __restrict__ Blo,
                 const float* __restrict__ bias, float* __restrict__ C,
                 int Nc, int K, int sigmoidFlag)
{
    extern __shared__ char sm[];
    const uint32_t sbase = smem_u32(sm);
    const int t = threadIdx.x;
    const int wid = t >> 5, lane = t & 31;
    const int wm = wid & 3;        // 0..3 -> m offset 32*wm
    const int wn = wid >> 2;       // 0..1 -> n offset 64*wn
    const int m0 = blockIdx.y * GBM;
    const int n0 = blockIdx.x * GBN;

    const int KITERS = K / GBK;    // 32

    float acc[2][8][4];
#pragma unroll
    for (int mi = 0; mi < 2; mi++)
#pragma unroll
        for (int ni = 0; ni < 8; ni++)
#pragma unroll
            for (int v = 0; v < 4; v++) acc[mi][ni][v] = 0.f;

    // prologue: stages 0..NSTAGE-2
#pragma unroll
    for (int s = 0; s < NSTAGE - 1; s++)
        load_stage(sbase, s, Ahi, Alo, Bhi, Blo, m0, n0, K, s * GBK, t);

    // ldmatrix address components
    const uint32_t a_off = (wm * 32 + (lane & 15)) * ROWB + (lane >> 4) * 16;
    const uint32_t b_off = (wn * 64 + (lane & 7)) * ROWB + ((lane >> 3) & 1) * 16;

    for (int it = 0; it < KITERS; it++) {
        CP_WAIT(NSTAGE - 2);
        __syncthreads();

        const int kload = it + NSTAGE - 1;
        if (kload < KITERS)
            load_stage(sbase, kload % NSTAGE, Ahi, Alo, Bhi, Blo, m0, n0, K, kload * GBK, t);

        const uint32_t st = sbase + (it % NSTAGE) * STAGEB;
#pragma unroll
        for (int ks = 0; ks < 2; ks++) {
            const uint32_t kb = ks * 32;
            uint32_t ah[2][4], al[2][4], bh[8][2], bl[8][2];
#pragma unroll
            for (int mi = 0; mi < 2; mi++) {
                const uint32_t ar = st + a_off + mi * (16 * ROWB) + kb;
                LDSM4(ah[mi][0], ah[mi][1], ah[mi][2], ah[mi][3], ar);
                LDSM4(al[mi][0], al[mi][1], al[mi][2], al[mi][3], ar + TILEB);
            }
#pragma unroll
            for (int ni = 0; ni < 8; ni++) {
                const uint32_t br = st + 2 * TILEB + b_off + ni * (8 * ROWB) + kb;
                LDSM2(bh[ni][0], bh[ni][1], br);
                LDSM2(bl[ni][0], bl[ni][1], br + TILEB);
            }
#pragma unroll
            for (int mi = 0; mi < 2; mi++)
#pragma unroll
                for (int ni = 0; ni < 8; ni++) {
                    MMA16816(acc[mi][ni], ah[mi], bh[ni]);
                    MMA16816(acc[mi][ni], ah[mi], bl[ni]);
                    MMA16816(acc[mi][ni], al[mi], bh[ni]);
                }
        }
    }

    // -------- epilogue: bias (+ optional sigmoid), fp32 store ---------------
    const int mrow = m0 + wm * 32 + (lane >> 2);
    const int ncol = n0 + wn * 64 + (lane & 3) * 2;
#pragma unroll
    for (int mi = 0; mi < 2; mi++) {
#pragma unroll
        for (int ni = 0; ni < 8; ni++) {
            const int cbase = ncol + ni * 8;
            const float b0 = __ldg(&bias[cbase]);
            const float b1 = __ldg(&bias[cbase + 1]);
            float v0 = acc[mi][ni][0] + b0, v1 = acc[mi][ni][1] + b1;
            float v2 = acc[mi][ni][2] + b0, v3 = acc[mi][ni][3] + b1;
            if (sigmoidFlag) {
                v0 = 1.f / (1.f + __expf(-v0)); v1 = 1.f / (1.f + __expf(-v1));
                v2 = 1.f / (1.f + __expf(-v2)); v3 = 1.f / (1.f + __expf(-v3));
            }
            const int r0 = mrow + mi * 16;
            *(float2*)(C + (size_t)r0 * Nc + cbase)       = make_float2(v0, v1);
            *(float2*)(C + (size_t)(r0 + 8) * Nc + cbase) = make_float2(v2, v3);
        }
    }
}

// ---------------- split fp32 -> bf16 hi/lo -----------------------------------
__global__ __launch_bounds__(256)
void split_kernel(const float4* __restrict__ src, __nv_bfloat162* __restrict__ hi,
                  __nv_bfloat162* __restrict__ lo, int n4)
{
    const int i = blockIdx.x * blockDim.x + threadIdx.x;
    if (i >= n4) return;
    const float4 v = src[i];
    __nv_bfloat16 h0 = __float2bfloat16(v.x), h1 = __float2bfloat16(v.y);
    __nv_bfloat16 h2 = __float2bfloat16(v.z), h3 = __float2bfloat16(v.w);
    __nv_bfloat16 l0 = __float2bfloat16(v.x - __bfloat162float(h0));
    __nv_bfloat16 l1 = __float2bfloat16(v.y - __bfloat162float(h1));
    __nv_bfloat16 l2 = __float2bfloat16(v.z - __bfloat162float(h2));
    __nv_bfloat16 l3 = __float2bfloat16(v.w - __bfloat162float(h3));
    hi[2 * i]     = __halves2bfloat162(h0, h1);
    hi[2 * i + 1] = __halves2bfloat162(h2, h3);
    lo[2 * i]     = __halves2bfloat162(l0, l1);
    lo[2 * i + 1] = __halves2bfloat162(l2, l3);
}

// -------- stage: per-position gains (softmax over S) + field = v * ||k|| -----
__global__ __launch_bounds__(256)
void gains_field_kernel(const float* __restrict__ qkv,
                        const float* __restrict__ Wqs,
                        const float* __restrict__ scale_gain)
{
    const int warpsPerBlock = blockDim.x >> 5;
    const int wid = blockIdx.x * warpsPerBlock + (threadIdx.x >> 5);
    if (wid >= B_ * H_ * N_) return;
    const int lane = threadIdx.x & 31;

    const int n  = wid & (N_ - 1);
    const int bh = wid >> 11;
    const int h  = bh & (H_ - 1);
    const int b  = bh >> 4;

    const float* base = qkv + (size_t)(b * N_ + n) * (3 * D_) + h * HD_;
    const float q0 = base[lane],            q1 = base[lane + 32];
    const float k0 = base[D_ + lane],       k1 = base[D_ + lane + 32];
    const float v0 = base[2 * D_ + lane],   v1 = base[2 * D_ + lane + 32];

    float ks = k0 * k0 + k1 * k1;
#pragma unroll
    for (int o = 16; o > 0; o >>= 1) ks += __shfl_xor_sync(0xffffffffu, ks, o);
    const float kmag = sqrtf(ks);

    const size_t fbase = ((size_t)bh * N_ + n) * HD_;
    g_field[fbase + lane]      = v0 * kmag;
    g_field[fbase + lane + 32] = v1 * kmag;

    float logit[S_];
#pragma unroll
    for (int s = 0; s < S_; s++) {
        float p = q0 * __ldg(&Wqs[s * HD_ + lane]) + q1 * __ldg(&Wqs[s * HD_ + lane + 32]);
#pragma unroll
        for (int o = 16; o > 0; o >>= 1) p += __shfl_xor_sync(0xffffffffu, p, o);
        logit[s] = p + __ldg(&scale_gain[s * H_ + h]);
    }
    float mx = logit[0];
#pragma unroll
    for (int s = 1; s < S_; s++) mx = fmaxf(mx, logit[s]);
    float e[S_], sum = 0.f;
#pragma unroll
    for (int s = 0; s < S_; s++) { e[s] = __expf(logit[s] - mx); sum += e[s]; }
    const float inv = 1.f / sum;

    const size_t gbase = (size_t)wid * S_;
#pragma unroll
    for (int s = 0; s < S_; s++)
        if (lane == s) g_gains[gbase + s] = e[s] * inv;
}

// -------- stage: causal multiscale dilated D4 conv ---------------------------
__global__ __launch_bounds__(256)
void conv_kernel()
{
    const int bh = blockIdx.y;
    const int n  = blockIdx.x * 4 + (threadIdx.x >> 6);
    const int hd = threadIdx.x & 63;

    const float* fbase = g_field + (size_t)bh * N_ * HD_;
    const size_t gidx = ((size_t)bh * N_ + n) * S_;

    float g[S_];
#pragma unroll
    for (int s = 0; s < S_; s++) g[s] = __ldg(&g_gains[gidx + s]);

    float acc = D4_3 * fbase[(size_t)n * HD_ + hd];

#pragma unroll
    for (int j = 0; j < S_; j++) {
        const int d = 1 << j;
        const int s3 = n - 3 * d, s2 = n - 2 * d, s1 = n - d;
        if (s3 >= 0) acc = fmaf(g[j] * D4_0, fbase[(size_t)s3 * HD_ + hd], acc);
        if (s2 >= 0) acc = fmaf(g[j] * D4_1, fbase[(size_t)s2 * HD_ + hd], acc);
        if (s1 >= 0) acc = fmaf(g[j] * D4_2, fbase[(size_t)s1 * HD_ + hd], acc);
    }
    g_outf[((size_t)bh * N_ + n) * HD_ + hd] = acc;
}

// -------- stage: head coupling + gate; emits bf16 hi/lo of G -----------------
__global__ __launch_bounds__(256)
void couple_gate_kernel(const float* __restrict__ fc)
{
    __shared__ float sf[H_ * HD_];
    __shared__ float cp[H_][H_];

    const int bn = blockIdx.x;
    const int b  = bn >> 11;
    const int n  = bn & (N_ - 1);
    const int tid = threadIdx.x;

#pragma unroll
    for (int r = 0; r < 4; r++) {
        const int idx = tid + r * 256;
        sf[idx] = g_outf[(((size_t)(b * H_ + (idx >> 6))) * N_ + n) * HD_ + (idx & 63)];
    }
    if (tid < H_) {
        float row[H_];
        float mx = -1e30f;
#pragma unroll
        for (int j = 0; j < H_; j++) { row[j] = fc[tid * H_ + j]; mx = fmaxf(mx, row[j]); }
        float sum = 0.f;
#pragma unroll
        for (int j = 0; j < H_; j++) { row[j] = __expf(row[j] - mx); sum += row[j]; }
        const float inv = 1.f / sum;
#pragma unroll
        for (int j = 0; j < H_; j++) cp[tid][j] = row[j] * inv;
    }
    __syncthreads();

    const size_t grow = ((size_t)b * N_ + n) * D_;
#pragma unroll
    for (int r = 0; r < 4; r++) {
        const int idx = tid + r * 256;
        const int i = idx >> 6, hd = idx & 63;
        float acc = 0.f;
#pragma unroll
        for (int j = 0; j < H_; j++) acc = fmaf(cp[i][j], sf[j * HD_ + hd], acc);
        const float v = acc * g_gate[grow + idx];
        const __nv_bfloat16 h = __float2bfloat16(v);
        g_Ghi[grow + idx] = h;
        g_Glo[grow + idx] = __float2bfloat16(v - __bfloat162float(h));
    }
}

// ------------------------------- launch --------------------------------------
extern "C" void kernel_launch(void* const* d_in, const int* in_sizes, int n_in,
                              void* d_out, int out_size)
{
    const float* x    = (const float*)d_in[0];
    const float* Wqkv = (const float*)d_in[1];
    const float* bqkv = (const float*)d_in[2];
    const float* Wo   = (const float*)d_in[3];
    const float* bo   = (const float*)d_in[4];
    const float* Wg   = (const float*)d_in[5];
    const float* bg   = (const float*)d_in[6];
    const float* scale_gain = (const float*)d_in[7];
    const float* Wqs  = (const float*)d_in[8];
    const float* fc   = (const float*)d_in[9];
    float* out = (float*)d_out;

    float *p_qkv, *p_gate;
    __nv_bfloat16 *p_xhi, *p_xlo, *p_Ghi, *p_Glo;
    __nv_bfloat16 *p_Wqkvhi, *p_Wqkvlo, *p_Wghi, *p_Wglo, *p_Wohi, *p_Wolo;
    cudaGetSymbolAddress((void**)&p_qkv,  g_qkv);
    cudaGetSymbolAddress((void**)&p_gate, g_gate);
    cudaGetSymbolAddress((void**)&p_xhi, g_xhi);   cudaGetSymbolAddress((void**)&p_xlo, g_xlo);
    cudaGetSymbolAddress((void**)&p_Ghi, g_Ghi);   cudaGetSymbolAddress((void**)&p_Glo, g_Glo);
    cudaGetSymbolAddress((void**)&p_Wqkvhi, g_Wqkvhi);
    cudaGetSymbolAddress((void**)&p_Wqkvlo, g_Wqkvlo);
    cudaGetSymbolAddress((void**)&p_Wghi, g_Wghi); cudaGetSymbolAddress((void**)&p_Wglo, g_Wglo);
    cudaGetSymbolAddress((void**)&p_Wohi, g_Wohi); cudaGetSymbolAddress((void**)&p_Wolo, g_Wolo);

    cudaFuncSetAttribute(gemm_bf16x3, cudaFuncAttributeMaxDynamicSharedMemorySize, GEMM_SMEM);

    // 0) split x and weights into bf16 hi/lo
    {
        int n4 = M_ * D_ / 4;
        split_kernel<<<(n4 + 255) / 256, 256>>>((const float4*)x,
            (__nv_bfloat162*)p_xhi, (__nv_bfloat162*)p_xlo, n4);
        n4 = 3 * D_ * D_ / 4;
        split_kernel<<<(n4 + 255) / 256, 256>>>((const float4*)Wqkv,
            (__nv_bfloat162*)p_Wqkvhi, (__nv_bfloat162*)p_Wqkvlo, n4);
        n4 = D_ * D_ / 4;
        split_kernel<<<(n4 + 255) / 256, 256>>>((const float4*)Wg,
            (__nv_bfloat162*)p_Wghi, (__nv_bfloat162*)p_Wglo, n4);
        split_kernel<<<(n4 + 255) / 256, 256>>>((const float4*)Wo,
            (__nv_bfloat162*)p_Wohi, (__nv_bfloat162*)p_Wolo, n4);
    }

    // 1) qkv = x @ Wqkv^T + bqkv
    {
        dim3 grid(3 * D_ / GBN, M_ / GBM);
        gemm_bf16x3<<<grid, 256, GEMM_SMEM>>>(p_xhi, p_xlo, p_Wqkvhi, p_Wqkvlo,
                                              bqkv, p_qkv, 3 * D_, D_, 0);
    }
    // 2) gate = sigmoid(x @ Wg^T + bg)
    {
        dim3 grid(D_ / GBN, M_ / GBM);
        gemm_bf16x3<<<grid, 256, GEMM_SMEM>>>(p_xhi, p_xlo, p_Wghi, p_Wglo,
                                              bg, p_gate, D_, D_, 1);
    }
    // 3) gains + field
    {
        const int totalWarps = B_ * H_ * N_;
        gains_field_kernel<<<totalWarps / 8, 8 * 32>>>(p_qkv, Wqs, scale_gain);
    }
    // 4) multiscale causal conv
    {
        dim3 grid(N_ / 4, B_ * H_);
        conv_kernel<<<grid, 256>>>();
    }
    // 5) head coupling + gate (emits bf16 hi/lo of G)
    couple_gate_kernel<<<B_ * N_, 256>>>(fc);

    // 6) out = G @ Wo^T + bo
    {
        dim3 grid(D_ / GBN, M_ / GBM);
        gemm_bf16x3<<<grid, 256, GEMM_SMEM>>>(p_Ghi, p_Glo, p_Wohi, p_Wolo,
                                              bo, out, D_, D_, 0);
    }
}

// round 4
// speedup vs baseline: 2.7712x; 1.2346x over previous
#include <cuda_runtime.h>
#include <cuda_bf16.h>
#include <math.h>
#include <stdint.h>

// Problem dims (fixed by the reference)
#define B_    4
#define N_    2048
#define D_    1024
#define H_    16
#define HD_   64
#define S_    11
#define M_    (B_ * N_)   // 8192

#define D4_0 0.4829629131445341f
#define D4_1 0.8365163037378079f
#define D4_2 0.2241438680420134f
#define D4_3 (-0.1294095225512604f)

// ---------------- scratch (static device globals; no allocation) -------------
__device__ __align__(256) float g_qkv [M_ * 3 * D_];
__device__ __align__(256) float g_gate[M_ * D_];
__device__ __align__(256) float g_field[B_ * H_ * N_ * HD_];
__device__ __align__(256) float g_gains[B_ * H_ * N_ * S_];
__device__ __align__(256) float g_outf [B_ * H_ * N_ * HD_];

__device__ __align__(256) __nv_bfloat16 g_xhi[M_ * D_];
__device__ __align__(256) __nv_bfloat16 g_xlo[M_ * D_];
__device__ __align__(256) __nv_bfloat16 g_Ghi[M_ * D_];
__device__ __align__(256) __nv_bfloat16 g_Glo[M_ * D_];
__device__ __align__(256) __nv_bfloat16 g_Wqkvhi[3 * D_ * D_];
__device__ __align__(256) __nv_bfloat16 g_Wqkvlo[3 * D_ * D_];
__device__ __align__(256) __nv_bfloat16 g_Wghi[D_ * D_];
__device__ __align__(256) __nv_bfloat16 g_Wglo[D_ * D_];
__device__ __align__(256) __nv_bfloat16 g_Wohi[D_ * D_];
__device__ __align__(256) __nv_bfloat16 g_Wolo[D_ * D_];

// ============================ PTX helpers ====================================
__device__ __forceinline__ uint32_t smem_u32(const void* p) {
    uint32_t a;
    asm("{ .reg .u64 t; cvta.to.shared.u64 t, %1; cvt.u32.u64 %0, t; }" : "=r"(a) : "l"(p));
    return a;
}

#define CP_ASYNC_16(sp, gp) \
    asm volatile("cp.async.cg.shared.global [%0], [%1], 16;" :: "r"(sp), "l"(gp) : "memory")
#define CP_COMMIT() asm volatile("cp.async.commit_group;" ::: "memory")
#define CP_WAIT(n)  asm volatile("cp.async.wait_group %0;" :: "n"(n) : "memory")

#define LDSM4(r0, r1, r2, r3, addr) \
    asm volatile("ldmatrix.sync.aligned.m8n8.x4.shared.b16 {%0,%1,%2,%3}, [%4];" \
        : "=r"(r0), "=r"(r1), "=r"(r2), "=r"(r3) : "r"(addr))
#define LDSM2(r0, r1, addr) \
    asm volatile("ldmatrix.sync.aligned.m8n8.x2.shared.b16 {%0,%1}, [%2];" \
        : "=r"(r0), "=r"(r1) : "r"(addr))

#define MMA16816(d, a, b) \
    asm volatile("mma.sync.aligned.m16n8k16.row.col.f32.bf16.bf16.f32 " \
        "{%0,%1,%2,%3}, {%4,%5,%6,%7}, {%8,%9}, {%0,%1,%2,%3};" \
        : "+f"((d)[0]), "+f"((d)[1]), "+f"((d)[2]), "+f"((d)[3]) \
        : "r"((a)[0]), "r"((a)[1]), "r"((a)[2]), "r"((a)[3]), "r"((b)[0]), "r"((b)[1]))

// ======================= bf16 multi-pass tensor-core GEMM ====================
// C[M, Nc] = A[M, K] @ W[Nc, K]^T + bias
// NPASS=1: Ahi*Bhi;  NPASS=2: +Alo*Bhi;  NPASS=3: +Ahi*Blo
#define GBM 128
#define GBN 128
#define GBK 32
#define NSTAGE 4
#define ROWB   80
#define TILEB  (128 * ROWB)

template<int NPASS, bool SIG>
__global__ __launch_bounds__(256, 1)
void gemm_bf16(const __nv_bfloat16* __restrict__ Ahi, const __nv_bfloat16* __restrict__ Alo,
               const __nv_bfloat16* __restrict__ Bhi, const __nv_bfloat16* __restrict__ Blo,
               const float* __restrict__ bias, float* __restrict__ C,
               int ldc, int K)
{
    constexpr int NT      = (NPASS == 1) ? 2 : (NPASS == 2 ? 3 : 4);
    constexpr int T_BHI   = (NPASS == 1) ? 1 : 2;
    constexpr int STAGEB  = NT * TILEB;

    extern __shared__ char sm[];
    const uint32_t sbase = smem_u32(sm);
    const int t = threadIdx.x;
    const int wid = t >> 5, lane = t & 31;
    const int wm = wid & 3;
    const int wn = wid >> 2;
    const int m0 = blockIdx.y * GBM;
    const int n0 = blockIdx.x * GBN;

    const int KITERS = K / GBK;

    float acc[2][8][4];
#pragma unroll
    for (int mi = 0; mi < 2; mi++)
#pragma unroll
        for (int ni = 0; ni < 8; ni++)
#pragma unroll
            for (int v = 0; v < 4; v++) acc[mi][ni][v] = 0.f;

    auto load_stage = [&](int stage, int kk) {
        const uint32_t sb = sbase + stage * STAGEB;
        const int r = t >> 2;
        const int c = t & 3;
#pragma unroll
        for (int j = 0; j < 2 * NT; j++) {
            const int tile = j >> 1;
            const int row  = ((j & 1) << 6) + r;
            const __nv_bfloat16* g;
            int grow;
            if (tile == 0)                      { g = Ahi; grow = m0 + row; }
            else if (NPASS >= 2 && tile == 1)   { g = Alo; grow = m0 + row; }
            else if (tile == T_BHI)             { g = Bhi; grow = n0 + row; }
            else                                { g = Blo; grow = n0 + row; }
            CP_ASYNC_16(sb + tile * TILEB + row * ROWB + c * 16,
                        g + (size_t)grow * K + kk + c * 8);
        }
        CP_COMMIT();
    };

#pragma unroll
    for (int s = 0; s < NSTAGE - 1; s++)
        load_stage(s, s * GBK);

    const uint32_t a_off = (wm * 32 + (lane & 15)) * ROWB + (lane >> 4) * 16;
    const uint32_t b_off = (wn * 64 + (lane & 7)) * ROWB + ((lane >> 3) & 1) * 16;

    for (int it = 0; it < KITERS; it++) {
        CP_WAIT(NSTAGE - 2);
        __syncthreads();

        const int kload = it + NSTAGE - 1;
        if (kload < KITERS)
            load_stage(kload % NSTAGE, kload * GBK);

        const uint32_t st = sbase + (it % NSTAGE) * STAGEB;
#pragma unroll
        for (int ks = 0; ks < 2; ks++) {
            const uint32_t kb = ks * 32;
            uint32_t ah[2][4], al[2][4], bh[8][2], bl[8][2];
#pragma unroll
            for (int mi = 0; mi < 2; mi++) {
                const uint32_t ar = st + a_off + mi * (16 * ROWB) + kb;
                LDSM4(ah[mi][0], ah[mi][1], ah[mi][2], ah[mi][3], ar);
                if (NPASS >= 2) LDSM4(al[mi][0], al[mi][1], al[mi][2], al[mi][3], ar + TILEB);
            }
#pragma unroll
            for (int ni = 0; ni < 8; ni++) {
                const uint32_t br = st + T_BHI * TILEB + b_off + ni * (8 * ROWB) + kb;
                LDSM2(bh[ni][0], bh[ni][1], br);
                if (NPASS == 3) LDSM2(bl[ni][0], bl[ni][1], br + TILEB);
            }
#pragma unroll
            for (int mi = 0; mi < 2; mi++)
#pragma unroll
                for (int ni = 0; ni < 8; ni++) {
                    MMA16816(acc[mi][ni], ah[mi], bh[ni]);
                    if (NPASS >= 2) MMA16816(acc[mi][ni], al[mi], bh[ni]);
                    if (NPASS == 3) MMA16816(acc[mi][ni], ah[mi], bl[ni]);
                }
        }
    }

    const int mrow = m0 + wm * 32 + (lane >> 2);
    const int ncol = n0 + wn * 64 + (lane & 3) * 2;
#pragma unroll
    for (int mi = 0; mi < 2; mi++) {
#pragma unroll
        for (int ni = 0; ni < 8; ni++) {
            const int cbase = ncol + ni * 8;
            const float b0 = __ldg(&bias[cbase]);
            const float b1 = __ldg(&bias[cbase + 1]);
            float v0 = acc[mi][ni][0] + b0, v1 = acc[mi][ni][1] + b1;
            float v2 = acc[mi][ni][2] + b0, v3 = acc[mi][ni][3] + b1;
            if (SIG) {
                v0 = 1.f / (1.f + __expf(-v0)); v1 = 1.f / (1.f + __expf(-v1));
                v2 = 1.f / (1.f + __expf(-v2)); v3 = 1.f / (1.f + __expf(-v3));
            }
            const int r0 = mrow + mi * 16;
            *(float2*)(C + (size_t)r0 * ldc + cbase)       = make_float2(v0, v1);
            *(float2*)(C + (size_t)(r0 + 8) * ldc + cbase) = make_float2(v2, v3);
        }
    }
}

// ---------------- split fp32 -> bf16 hi/lo -----------------------------------
__global__ __launch_bounds__(256)
void split_kernel(const float4* __restrict__ src, __nv_bfloat162* __restrict__ hi,
                  __nv_bfloat162* __restrict__ lo, int n4)
{
    const int i = blockIdx.x * blockDim.x + threadIdx.x;
    if (i >= n4) return;
    const float4 v = src[i];
    __nv_bfloat16 h0 = __float2bfloat16(v.x), h1 = __float2bfloat16(v.y);
    __nv_bfloat16 h2 = __float2bfloat16(v.z), h3 = __float2bfloat16(v.w);
    __nv_bfloat16 l0 = __float2bfloat16(v.x - __bfloat162float(h0));
    __nv_bfloat16 l1 = __float2bfloat16(v.y - __bfloat162float(h1));
    __nv_bfloat16 l2 = __float2bfloat16(v.z - __bfloat162float(h2));
    __nv_bfloat16 l3 = __float2bfloat16(v.w - __bfloat162float(h3));
    hi[2 * i]     = __halves2bfloat162(h0, h1);
    hi[2 * i + 1] = __halves2bfloat162(h2, h3);
    lo[2 * i]     = __halves2bfloat162(l0, l1);
    lo[2 * i + 1] = __halves2bfloat162(l2, l3);
}

// hi-only split (for weights whose lo term is never used)
__global__ __launch_bounds__(256)
void splith_kernel(const float4* __restrict__ src, __nv_bfloat162* __restrict__ hi, int n4)
{
    const int i = blockIdx.x * blockDim.x + threadIdx.x;
    if (i >= n4) return;
    const float4 v = src[i];
    hi[2 * i]     = __halves2bfloat162(__float2bfloat16(v.x), __float2bfloat16(v.y));
    hi[2 * i + 1] = __halves2bfloat162(__float2bfloat16(v.z), __float2bfloat16(v.w));
}

// -------- stage: per-position gains (softmax over S) + field = v * ||k|| -----
__global__ __launch_bounds__(256)
void gains_field_kernel(const float* __restrict__ qkv,
                        const float* __restrict__ Wqs,
                        const float* __restrict__ scale_gain)
{
    const int warpsPerBlock = blockDim.x >> 5;
    const int wid = blockIdx.x * warpsPerBlock + (threadIdx.x >> 5);
    if (wid >= B_ * H_ * N_) return;
    const int lane = threadIdx.x & 31;

    const int n  = wid & (N_ - 1);
    const int bh = wid >> 11;
    const int h  = bh & (H_ - 1);
    const int b  = bh >> 4;

    const float* base = qkv + (size_t)(b * N_ + n) * (3 * D_) + h * HD_;
    const float q0 = base[lane],            q1 = base[lane + 32];
    const float k0 = base[D_ + lane],       k1 = base[D_ + lane + 32];
    const float v0 = base[2 * D_ + lane],   v1 = base[2 * D_ + lane + 32];

    float ks = k0 * k0 + k1 * k1;
#pragma unroll
    for (int o = 16; o > 0; o >>= 1) ks += __shfl_xor_sync(0xffffffffu, ks, o);
    const float kmag = sqrtf(ks);

    const size_t fbase = ((size_t)bh * N_ + n) * HD_;
    g_field[fbase + lane]      = v0 * kmag;
    g_field[fbase + lane + 32] = v1 * kmag;

    float logit[S_];
#pragma unroll
    for (int s = 0; s < S_; s++) {
        float p = q0 * __ldg(&Wqs[s * HD_ + lane]) + q1 * __ldg(&Wqs[s * HD_ + lane + 32]);
#pragma unroll
        for (int o = 16; o > 0; o >>= 1) p += __shfl_xor_sync(0xffffffffu, p, o);
        logit[s] = p + __ldg(&scale_gain[s * H_ + h]);
    }
    float mx = logit[0];
#pragma unroll
    for (int s = 1; s < S_; s++) mx = fmaxf(mx, logit[s]);
    float e[S_], sum = 0.f;
#pragma unroll
    for (int s = 0; s < S_; s++) { e[s] = __expf(logit[s] - mx); sum += e[s]; }
    const float inv = 1.f / sum;

    const size_t gbase = (size_t)wid * S_;
#pragma unroll
    for (int s = 0; s < S_; s++)
        if (lane == s) g_gains[gbase + s] = e[s] * inv;
}

// -------- stage: causal multiscale dilated D4 conv (smem-slab version) -------
// block = (bh, 16-hd chunk); whole 2048 x 16 field column staged in smem
#define CONV_SMEM (N_ * 16 * 4)   // 131072 B

__global__ __launch_bounds__(512)
void conv_kernel2()
{
    extern __shared__ float slab[];          // [2048][16]
    const int bh  = blockIdx.y;
    const int hd0 = blockIdx.x * 16;
    const int t   = threadIdx.x;

    const float* fb = g_field + (size_t)bh * N_ * HD_;
#pragma unroll
    for (int i = 0; i < 16; i++) {
        const int idx = i * 512 + t;         // 8192 float4
        const int n = idx >> 2, c = idx & 3;
        ((float4*)slab)[idx] = *(const float4*)(fb + (size_t)n * HD_ + hd0 + c * 4);
    }
    __syncthreads();

    const int hd = t & 15, nb = t >> 4;
    for (int ni = 0; ni < 64; ni++) {
        const int n = ni * 32 + nb;
        const float* gp = g_gains + ((size_t)bh * N_ + n) * S_;

        float acc = D4_3 * slab[n * 16 + hd];
#pragma unroll
        for (int j = 0; j < S_; j++) {
            const int d = 1 << j;
            const float g = __ldg(&gp[j]);
            const int s3 = n - 3 * d, s2 = n - 2 * d, s1 = n - d;
            if (s3 >= 0) acc = fmaf(g * D4_0, slab[s3 * 16 + hd], acc);
            if (s2 >= 0) acc = fmaf(g * D4_1, slab[s2 * 16 + hd], acc);
            if (s1 >= 0) acc = fmaf(g * D4_2, slab[s1 * 16 + hd], acc);
        }
        g_outf[((size_t)bh * N_ + n) * HD_ + hd0 + hd] = acc;
    }
}

// -------- stage: head coupling + gate; emits bf16 hi/lo of G -----------------
__global__ __launch_bounds__(256)
void couple_gate_kernel(const float* __restrict__ fc)
{
    __shared__ float sf[H_ * HD_];
    __shared__ float cp[H_][H_];

    const int bn = blockIdx.x;
    const int b  = bn >> 11;
    const int n  = bn & (N_ - 1);
    const int tid = threadIdx.x;

#pragma unroll
    for (int r = 0; r < 4; r++) {
        const int idx = tid + r * 256;
        sf[idx] = g_outf[(((size_t)(b * H_ + (idx >> 6))) * N_ + n) * HD_ + (idx & 63)];
    }
    if (tid < H_) {
        float row[H_];
        float mx = -1e30f;
#pragma unroll
        for (int j = 0; j < H_; j++) { row[j] = fc[tid * H_ + j]; mx = fmaxf(mx, row[j]); }
        float sum = 0.f;
#pragma unroll
        for (int j = 0; j < H_; j++) { row[j] = __expf(row[j] - mx); sum += row[j]; }
        const float inv = 1.f / sum;
#pragma unroll
        for (int j = 0; j < H_; j++) cp[tid][j] = row[j] * inv;
    }
    __syncthreads();

    const size_t grow = ((size_t)b * N_ + n) * D_;
#pragma unroll
    for (int r = 0; r < 4; r++) {
        const int idx = tid + r * 256;
        const int i = idx >> 6, hd = idx & 63;
        float acc = 0.f;
#pragma unroll
        for (int j = 0; j < H_; j++) acc = fmaf(cp[i][j], sf[j * HD_ + hd], acc);
        const float v = acc * g_gate[grow + idx];
        const __nv_bfloat16 h = __float2bfloat16(v);
        g_Ghi[grow + idx] = h;
        g_Glo[grow + idx] = __float2bfloat16(v - __bfloat162float(h));
    }
}

// ------------------------------- launch --------------------------------------
extern "C" void kernel_launch(void* const* d_in, const int* in_sizes, int n_in,
                              void* d_out, int out_size)
{
    const float* x    = (const float*)d_in[0];
    const float* Wqkv = (const float*)d_in[1];
    const float* bqkv = (const float*)d_in[2];
    const float* Wo   = (const float*)d_in[3];
    const float* bo   = (const float*)d_in[4];
    const float* Wg   = (const float*)d_in[5];
    const float* bg   = (const float*)d_in[6];
    const float* scale_gain = (const float*)d_in[7];
    const float* Wqs  = (const float*)d_in[8];
    const float* fc   = (const float*)d_in[9];
    float* out = (float*)d_out;

    float *p_qkv, *p_gate;
    __nv_bfloat16 *p_xhi, *p_xlo, *p_Ghi, *p_Glo;
    __nv_bfloat16 *p_Wqkvhi, *p_Wqkvlo, *p_Wghi, *p_Wohi, *p_Wolo;
    cudaGetSymbolAddress((void**)&p_qkv,  g_qkv);
    cudaGetSymbolAddress((void**)&p_gate, g_gate);
    cudaGetSymbolAddress((void**)&p_xhi, g_xhi);   cudaGetSymbolAddress((void**)&p_xlo, g_xlo);
    cudaGetSymbolAddress((void**)&p_Ghi, g_Ghi);   cudaGetSymbolAddress((void**)&p_Glo, g_Glo);
    cudaGetSymbolAddress((void**)&p_Wqkvhi, g_Wqkvhi);
    cudaGetSymbolAddress((void**)&p_Wqkvlo, g_Wqkvlo);
    cudaGetSymbolAddress((void**)&p_Wghi, g_Wghi);
    cudaGetSymbolAddress((void**)&p_Wohi, g_Wohi); cudaGetSymbolAddress((void**)&p_Wolo, g_Wolo);

    cudaFuncSetAttribute(gemm_bf16<1, false>, cudaFuncAttributeMaxDynamicSharedMemorySize, NSTAGE * 2 * TILEB);
    cudaFuncSetAttribute(gemm_bf16<1, true>,  cudaFuncAttributeMaxDynamicSharedMemorySize, NSTAGE * 2 * TILEB);
    cudaFuncSetAttribute(gemm_bf16<2, false>, cudaFuncAttributeMaxDynamicSharedMemorySize, NSTAGE * 3 * TILEB);
    cudaFuncSetAttribute(gemm_bf16<3, false>, cudaFuncAttributeMaxDynamicSharedMemorySize, NSTAGE * 4 * TILEB);
    cudaFuncSetAttribute(conv_kernel2, cudaFuncAttributeMaxDynamicSharedMemorySize, CONV_SMEM);

    // 0) splits
    {
        int n4 = M_ * D_ / 4;
        split_kernel<<<(n4 + 255) / 256, 256>>>((const float4*)x,
            (__nv_bfloat162*)p_xhi, (__nv_bfloat162*)p_xlo, n4);
        n4 = 3 * D_ * D_ / 4;
        split_kernel<<<(n4 + 255) / 256, 256>>>((const float4*)Wqkv,
            (__nv_bfloat162*)p_Wqkvhi, (__nv_bfloat162*)p_Wqkvlo, n4);
        n4 = D_ * D_ / 4;
        splith_kernel<<<(n4 + 255) / 256, 256>>>((const float4*)Wg,
            (__nv_bfloat162*)p_Wghi, n4);
        split_kernel<<<(n4 + 255) / 256, 256>>>((const float4*)Wo,
            (__nv_bfloat162*)p_Wohi, (__nv_bfloat162*)p_Wolo, n4);
    }

    // 1) q = x @ Wq^T (1-pass), k (2-pass), v (3-pass) -> strided into g_qkv
    {
        dim3 grid(D_ / GBN, M_ / GBM);   // (8, 64)
        gemm_bf16<1, false><<<grid, 256, NSTAGE * 2 * TILEB>>>(
            p_xhi, p_xlo, p_Wqkvhi, p_Wqkvlo, bqkv, p_qkv, 3 * D_, D_);
        gemm_bf16<2, false><<<grid, 256, NSTAGE * 3 * TILEB>>>(
            p_xhi, p_xlo, p_Wqkvhi + (size_t)D_ * D_, p_Wqkvlo + (size_t)D_ * D_,
            bqkv + D_, p_qkv + D_, 3 * D_, D_);
        gemm_bf16<3, false><<<grid, 256, NSTAGE * 4 * TILEB>>>(
            p_xhi, p_xlo, p_Wqkvhi + (size_t)2 * D_ * D_, p_Wqkvlo + (size_t)2 * D_ * D_,
            bqkv + 2 * D_, p_qkv + 2 * D_, 3 * D_, D_);
    }
    // 2) gate = sigmoid(x @ Wg^T + bg)   (1-pass)
    {
        dim3 grid(D_ / GBN, M_ / GBM);
        gemm_bf16<1, true><<<grid, 256, NSTAGE * 2 * TILEB>>>(
            p_xhi, p_xlo, p_Wghi, p_Wghi, bg, p_gate, D_, D_);
    }
    // 3) gains + field
    {
        const int totalWarps = B_ * H_ * N_;
        gains_field_kernel<<<totalWarps / 8, 8 * 32>>>(p_qkv, Wqs, scale_gain);
    }
    // 4) multiscale causal conv (smem slab)
    {
        dim3 grid(HD_ / 16, B_ * H_);    // (4, 64)
        conv_kernel2<<<grid, 512, CONV_SMEM>>>();
    }
    // 5) head coupling + gate (emits bf16 hi/lo of G)
    couple_gate_kernel<<<B_ * N_, 256>>>(fc);

    // 6) out = G @ Wo^T + bo   (3-pass)
    {
        dim3 grid(D_ / GBN, M_ / GBM);
        gemm_bf16<3, false><<<grid, 256, NSTAGE * 4 * TILEB>>>(
            p_Ghi, p_Glo, p_Wohi, p_Wolo, bo, out, D_, D_);
    }
}

// round 5
// speedup vs baseline: 3.9045x; 1.4089x over previous
#include <cuda_runtime.h>
#include <cuda_fp16.h>
#include <math.h>
#include <stdint.h>

// Problem dims (fixed by the reference)
#define B_    4
#define N_    2048
#define D_    1024
#define H_    16
#define HD_   64
#define S_    11
#define M_    (B_ * N_)   // 8192

#define D4_0 0.4829629131445341f
#define D4_1 0.8365163037378079f
#define D4_2 0.2241438680420134f
#define D4_3 (-0.1294095225512604f)

// ---------------- scratch (static device globals; no allocation) -------------
__device__ __align__(256) float g_qkv [M_ * 3 * D_];    // q cols unused now
__device__ __align__(256) float g_gate[M_ * D_];
__device__ __align__(256) float g_logits[M_ * 256];     // h*11+s cols (176 used)
__device__ __align__(256) float g_field[B_ * H_ * N_ * HD_];
__device__ __align__(256) float g_gains[B_ * H_ * N_ * S_];
__device__ __align__(256) float g_outf [B_ * H_ * N_ * HD_];
__device__ __align__(256) float g_zerobias[256];        // zero-filled by weff_kernel

__device__ __align__(256) __half g_xhi[M_ * D_];
__device__ __align__(256) __half g_xlo[M_ * D_];
__device__ __align__(256) __half g_Ghi[M_ * D_];
__device__ __align__(256) __half g_Glo[M_ * D_];
__device__ __align__(256) __half g_Wkvhi[2 * D_ * D_];  // Wk, Wv hi
__device__ __align__(256) __half g_Wghi[D_ * D_];
__device__ __align__(256) __half g_Wohi[D_ * D_];
__device__ __align__(256) __half g_Weffhi[256 * D_];    // rows 176..255 zero

// ============================ PTX helpers ====================================
__device__ __forceinline__ uint32_t smem_u32(const void* p) {
    uint32_t a;
    asm("{ .reg .u64 t; cvta.to.shared.u64 t, %1; cvt.u32.u64 %0, t; }" : "=r"(a) : "l"(p));
    return a;
}

#define CP_ASYNC_16(sp, gp) \
    asm volatile("cp.async.cg.shared.global [%0], [%1], 16;" :: "r"(sp), "l"(gp) : "memory")
#define CP_COMMIT() asm volatile("cp.async.commit_group;" ::: "memory")
#define CP_WAIT(n)  asm volatile("cp.async.wait_group %0;" :: "n"(n) : "memory")

#define LDSM4(r0, r1, r2, r3, addr) \
    asm volatile("ldmatrix.sync.aligned.m8n8.x4.shared.b16 {%0,%1,%2,%3}, [%4];" \
        : "=r"(r0), "=r"(r1), "=r"(r2), "=r"(r3) : "r"(addr))
#define LDSM2(r0, r1, addr) \
    asm volatile("ldmatrix.sync.aligned.m8n8.x2.shared.b16 {%0,%1}, [%2];" \
        : "=r"(r0), "=r"(r1) : "r"(addr))

#define MMA16816(d, a, b) \
    asm volatile("mma.sync.aligned.m16n8k16.row.col.f32.f16.f16.f32 " \
        "{%0,%1,%2,%3}, {%4,%5,%6,%7}, {%8,%9}, {%0,%1,%2,%3};" \
        : "+f"((d)[0]), "+f"((d)[1]), "+f"((d)[2]), "+f"((d)[3]) \
        : "r"((a)[0]), "r"((a)[1]), "r"((a)[2]), "r"((a)[3]), "r"((b)[0]), "r"((b)[1]))

// ======================= fp16 tensor-core GEMM building blocks ===============
#define GBM 128
#define GBN 128
#define GBK 32
#define NSTAGE 4
#define ROWB   80
#define TILEB  (128 * ROWB)

// ---- templated 2-pass GEMM: C = (Ahi+Alo) @ Bhi^T + bias --------------------
template<bool SIG>
__global__ __launch_bounds__(256, 1)
void gemm_2pass(const __half* __restrict__ Ahi, const __half* __restrict__ Alo,
                const __half* __restrict__ Bhi,
                const float* __restrict__ bias, float* __restrict__ C,
                int ldc, int K)
{
    constexpr int STAGEB = 3 * TILEB;
    extern __shared__ char smx[];
    const uint32_t sbase = smem_u32(smx);
    const int t = threadIdx.x;
    const int wid = t >> 5, lane = t & 31;
    const int wm = wid & 3, wn = wid >> 2;
    const int m0 = blockIdx.y * GBM;
    const int n0 = blockIdx.x * GBN;
    const int KITERS = K / GBK;

    float acc[2][8][4];
#pragma unroll
    for (int mi = 0; mi < 2; mi++)
#pragma unroll
        for (int ni = 0; ni < 8; ni++)
#pragma unroll
            for (int v = 0; v < 4; v++) acc[mi][ni][v] = 0.f;

    auto load_stage = [&](int stage, int kk) {
        const uint32_t sb = sbase + stage * STAGEB;
        const int r = t >> 2, c = t & 3;
#pragma unroll
        for (int j = 0; j < 6; j++) {
            const int tile = j >> 1;
            const int row  = ((j & 1) << 6) + r;
            const __half* g;
            int grow;
            if (tile == 0)      { g = Ahi; grow = m0 + row; }
            else if (tile == 1) { g = Alo; grow = m0 + row; }
            else                { g = Bhi; grow = n0 + row; }
            CP_ASYNC_16(sb + tile * TILEB + row * ROWB + c * 16,
                        g + (size_t)grow * K + kk + c * 8);
        }
        CP_COMMIT();
    };

#pragma unroll
    for (int s = 0; s < NSTAGE - 1; s++) load_stage(s, s * GBK);

    const uint32_t a_off = (wm * 32 + (lane & 15)) * ROWB + (lane >> 4) * 16;
    const uint32_t b_off = (wn * 64 + (lane & 7)) * ROWB + ((lane >> 3) & 1) * 16;

    for (int it = 0; it < KITERS; it++) {
        CP_WAIT(NSTAGE - 2);
        __syncthreads();
        const int kload = it + NSTAGE - 1;
        if (kload < KITERS) load_stage(kload % NSTAGE, kload * GBK);

        const uint32_t st = sbase + (it % NSTAGE) * STAGEB;
#pragma unroll
        for (int ks = 0; ks < 2; ks++) {
            const uint32_t kb = ks * 32;
            uint32_t ah[2][4], al[2][4], bh[8][2];
#pragma unroll
            for (int mi = 0; mi < 2; mi++) {
                const uint32_t ar = st + a_off + mi * (16 * ROWB) + kb;
                LDSM4(ah[mi][0], ah[mi][1], ah[mi][2], ah[mi][3], ar);
                LDSM4(al[mi][0], al[mi][1], al[mi][2], al[mi][3], ar + TILEB);
            }
#pragma unroll
            for (int ni = 0; ni < 8; ni++) {
                const uint32_t br = st + 2 * TILEB + b_off + ni * (8 * ROWB) + kb;
                LDSM2(bh[ni][0], bh[ni][1], br);
            }
#pragma unroll
            for (int mi = 0; mi < 2; mi++)
#pragma unroll
                for (int ni = 0; ni < 8; ni++) {
                    MMA16816(acc[mi][ni], ah[mi], bh[ni]);
                    MMA16816(acc[mi][ni], al[mi], bh[ni]);
                }
        }
    }

    const int mrow = m0 + wm * 32 + (lane >> 2);
    const int ncol = n0 + wn * 64 + (lane & 3) * 2;
#pragma unroll
    for (int mi = 0; mi < 2; mi++)
#pragma unroll
        for (int ni = 0; ni < 8; ni++) {
            const int cbase = ncol + ni * 8;
            const float b0 = __ldg(&bias[cbase]);
            const float b1 = __ldg(&bias[cbase + 1]);
            float v0 = acc[mi][ni][0] + b0, v1 = acc[mi][ni][1] + b1;
            float v2 = acc[mi][ni][2] + b0, v3 = acc[mi][ni][3] + b1;
            if (SIG) {
                v0 = 1.f / (1.f + __expf(-v0)); v1 = 1.f / (1.f + __expf(-v1));
                v2 = 1.f / (1.f + __expf(-v2)); v3 = 1.f / (1.f + __expf(-v3));
            }
            const int r0 = mrow + mi * 16;
            *(float2*)(C + (size_t)r0 * ldc + cbase)       = make_float2(v0, v1);
            *(float2*)(C + (size_t)(r0 + 8) * ldc + cbase) = make_float2(v2, v3);
        }
}

// ---- combined 1-pass GEMM: k | gate | logits in one launch ------------------
// bx 0..7: k = x@Wk^T + bqkv[D..2D)     -> g_qkv cols [D,2D), ldc 3D
// bx 8..15: gate = sigmoid(x@Wg^T + bg) -> g_gate, ldc D
// bx 16..17: logits = x@Weff^T          -> g_logits, ldc 256
__global__ __launch_bounds__(256, 1)
void gemm_1pass_combo(const __half* __restrict__ xhi,
                      const __half* __restrict__ Wk,
                      const __half* __restrict__ Wg,
                      const __half* __restrict__ Weff,
                      const float* __restrict__ bqkv1,
                      const float* __restrict__ bg,
                      float* __restrict__ Cqkv, float* __restrict__ Cgate,
                      float* __restrict__ Clog)
{
    constexpr int STAGEB = 2 * TILEB;
    constexpr int K = D_;
    extern __shared__ char smx[];
    const uint32_t sbase = smem_u32(smx);
    const int t = threadIdx.x;
    const int wid = t >> 5, lane = t & 31;
    const int wm = wid & 3, wn = wid >> 2;
    const int m0 = blockIdx.y * GBM;
    const int bx = blockIdx.x;

    const __half* Bp;
    float* C;
    const float* bias;
    int ldc, n0c;
    bool sig = false;
    if (bx < 8)       { Bp = Wk   + (size_t)bx * 128 * K;        C = Cqkv;  bias = bqkv1;      ldc = 3 * D_; n0c = bx * 128; }
    else if (bx < 16) { Bp = Wg   + (size_t)(bx - 8) * 128 * K;  C = Cgate; bias = bg;         ldc = D_;     n0c = (bx - 8) * 128; sig = true; }
    else              { Bp = Weff + (size_t)(bx - 16) * 128 * K; C = Clog;  bias = g_zerobias; ldc = 256;    n0c = (bx - 16) * 128; }

    const int KITERS = K / GBK;

    float acc[2][8][4];
#pragma unroll
    for (int mi = 0; mi < 2; mi++)
#pragma unroll
        for (int ni = 0; ni < 8; ni++)
#pragma unroll
            for (int v = 0; v < 4; v++) acc[mi][ni][v] = 0.f;

    auto load_stage = [&](int stage, int kk) {
        const uint32_t sb = sbase + stage * STAGEB;
        const int r = t >> 2, c = t & 3;
#pragma unroll
        for (int j = 0; j < 4; j++) {
            const int tile = j >> 1;
            const int row  = ((j & 1) << 6) + r;
            const __half* g = (tile == 0) ? xhi : Bp;
            const int grow  = (tile == 0) ? (m0 + row) : row;
            CP_ASYNC_16(sb + tile * TILEB + row * ROWB + c * 16,
                        g + (size_t)grow * K + kk + c * 8);
        }
        CP_COMMIT();
    };

#pragma unroll
    for (int s = 0; s < NSTAGE - 1; s++) load_stage(s, s * GBK);

    const uint32_t a_off = (wm * 32 + (lane & 15)) * ROWB + (lane >> 4) * 16;
    const uint32_t b_off = (wn * 64 + (lane & 7)) * ROWB + ((lane >> 3) & 1) * 16;

    for (int it = 0; it < KITERS; it++) {
        CP_WAIT(NSTAGE - 2);
        __syncthreads();
        const int kload = it + NSTAGE - 1;
        if (kload < KITERS) load_stage(kload % NSTAGE, kload * GBK);

        const uint32_t st = sbase + (it % NSTAGE) * STAGEB;
#pragma unroll
        for (int ks = 0; ks < 2; ks++) {
            const uint32_t kb = ks * 32;
            uint32_t ah[2][4], bh[8][2];
#pragma unroll
            for (int mi = 0; mi < 2; mi++) {
                const uint32_t ar = st + a_off + mi * (16 * ROWB) + kb;
                LDSM4(ah[mi][0], ah[mi][1], ah[mi][2], ah[mi][3], ar);
            }
#pragma unroll
            for (int ni = 0; ni < 8; ni++) {
                const uint32_t br = st + TILEB + b_off + ni * (8 * ROWB) + kb;
                LDSM2(bh[ni][0], bh[ni][1], br);
            }
#pragma unroll
            for (int mi = 0; mi < 2; mi++)
#pragma unroll
                for (int ni = 0; ni < 8; ni++)
                    MMA16816(acc[mi][ni], ah[mi], bh[ni]);
        }
    }

    const int mrow = m0 + wm * 32 + (lane >> 2);
    const int ncl  = wn * 64 + (lane & 3) * 2;   // local col within region tile set
#pragma unroll
    for (int mi = 0; mi < 2; mi++)
#pragma unroll
        for (int ni = 0; ni < 8; ni++) {
            const int cl = n0c + ncl + ni * 8;
            const float b0 = __ldg(&bias[cl]);
            const float b1 = __ldg(&bias[cl + 1]);
            float v0 = acc[mi][ni][0] + b0, v1 = acc[mi][ni][1] + b1;
            float v2 = acc[mi][ni][2] + b0, v3 = acc[mi][ni][3] + b1;
            if (sig) {
                v0 = 1.f / (1.f + __expf(-v0)); v1 = 1.f / (1.f + __expf(-v1));
                v2 = 1.f / (1.f + __expf(-v2)); v3 = 1.f / (1.f + __expf(-v3));
            }
            const int r0 = mrow + mi * 16;
            *(float2*)(C + (size_t)r0 * ldc + cl)       = make_float2(v0, v1);
            *(float2*)(C + (size_t)(r0 + 8) * ldc + cl) = make_float2(v2, v3);
        }
}

// ---------------- splits ------------------------------------------------------
__global__ __launch_bounds__(256)
void split_kernel(const float4* __restrict__ src, __half2* __restrict__ hi,
                  __half2* __restrict__ lo, int n4)
{
    const int i = blockIdx.x * blockDim.x + threadIdx.x;
    if (i >= n4) return;
    const float4 v = src[i];
    const __half h0 = __float2half(v.x), h1 = __float2half(v.y);
    const __half h2 = __float2half(v.z), h3 = __float2half(v.w);
    hi[2 * i]     = __halves2half2(h0, h1);
    hi[2 * i + 1] = __halves2half2(h2, h3);
    lo[2 * i]     = __halves2half2(__float2half(v.x - __half2float(h0)),
                                   __float2half(v.y - __half2float(h1)));
    lo[2 * i + 1] = __halves2half2(__float2half(v.z - __half2float(h2)),
                                   __float2half(v.w - __half2float(h3)));
}

__global__ __launch_bounds__(256)
void splith_kernel(const float4* __restrict__ src, __half2* __restrict__ hi, int n4)
{
    const int i = blockIdx.x * blockDim.x + threadIdx.x;
    if (i >= n4) return;
    const float4 v = src[i];
    hi[2 * i]     = __halves2half2(__float2half(v.x), __float2half(v.y));
    hi[2 * i + 1] = __halves2half2(__float2half(v.z), __float2half(v.w));
}

// ---------------- Weff = Wqs @ Wq (per head), fp32 -> fp16 --------------------
// Weff[r, k] = sum_d Wqs[s,d] * Wqkv[h*64+d, k],  r = h*11+s  (r<176; else 0)
__global__ __launch_bounds__(256)
void weff_kernel(const float* __restrict__ Wqkv, const float* __restrict__ Wqs,
                 __half* __restrict__ Weff)
{
    const int r = blockIdx.y;
    const int k = blockIdx.x * 256 + threadIdx.x;
    float acc = 0.f;
    if (r < 176) {
        const int h = r / 11, s = r % 11;
        const float* wq = Wqkv + (size_t)(h * 64) * D_ + k;
        const float* ws = Wqs + s * HD_;
#pragma unroll 16
        for (int d = 0; d < 64; d++)
            acc = fmaf(__ldg(&ws[d]), __ldg(&wq[(size_t)d * D_]), acc);
    }
    Weff[(size_t)r * D_ + k] = __float2half(acc);
    if (r == 0 && blockIdx.x == 0) g_zerobias[threadIdx.x] = 0.f;
}

// -------- stage: gains (softmax over precomputed logits) + field = v*||k|| ---
__global__ __launch_bounds__(256)
void gains_field_kernel(const float* __restrict__ qkv,
                        const float* __restrict__ logits,
                        const float* __restrict__ scale_gain)
{
    const int wid = blockIdx.x * (blockDim.x >> 5) + (threadIdx.x >> 5);
    if (wid >= B_ * H_ * N_) return;
    const int lane = threadIdx.x & 31;

    const int n  = wid & (N_ - 1);
    const int bh = wid >> 11;
    const int h  = bh & (H_ - 1);
    const int b  = bh >> 4;

    const float* base = qkv + (size_t)(b * N_ + n) * (3 * D_) + h * HD_;
    const float k0 = base[D_ + lane],     k1 = base[D_ + lane + 32];
    const float v0 = base[2 * D_ + lane], v1 = base[2 * D_ + lane + 32];

    float ks = k0 * k0 + k1 * k1;
#pragma unroll
    for (int o = 16; o > 0; o >>= 1) ks += __shfl_xor_sync(0xffffffffu, ks, o);
    const float kmag = sqrtf(ks);

    const size_t fbase = ((size_t)bh * N_ + n) * HD_;
    g_field[fbase + lane]      = v0 * kmag;
    g_field[fbase + lane + 32] = v1 * kmag;

    float logit = -1e30f;
    if (lane < S_)
        logit = __ldg(&logits[((size_t)(b * N_ + n)) * 256 + h * S_ + lane])
              + __ldg(&scale_gain[lane * H_ + h]);
    float mx = logit;
#pragma unroll
    for (int o = 16; o > 0; o >>= 1) mx = fmaxf(mx, __shfl_xor_sync(0xffffffffu, mx, o));
    float e = (lane < S_) ? __expf(logit - mx) : 0.f;
    float sum = e;
#pragma unroll
    for (int o = 16; o > 0; o >>= 1) sum += __shfl_xor_sync(0xffffffffu, sum, o);
    if (lane < S_) g_gains[(size_t)wid * S_ + lane] = e / sum;
}

// -------- stage: causal multiscale dilated D4 conv (smem-slab) ----------------
#define CONV_SMEM (N_ * 16 * 4)   // 131072 B

__global__ __launch_bounds__(512)
void conv_kernel2()
{
    extern __shared__ float slab[];          // [2048][16]
    const int bh  = blockIdx.y;
    const int hd0 = blockIdx.x * 16;
    const int t   = threadIdx.x;

    const float* fb = g_field + (size_t)bh * N_ * HD_;
#pragma unroll
    for (int i = 0; i < 16; i++) {
        const int idx = i * 512 + t;
        const int n = idx >> 2, c = idx & 3;
        ((float4*)slab)[idx] = *(const float4*)(fb + (size_t)n * HD_ + hd0 + c * 4);
    }
    __syncthreads();

    const int hd = t & 15, nb = t >> 4;
    for (int ni = 0; ni < 64; ni++) {
        const int n = ni * 32 + nb;
        const float* gp = g_gains + ((size_t)bh * N_ + n) * S_;

        float acc = D4_3 * slab[n * 16 + hd];
#pragma unroll
        for (int j = 0; j < S_; j++) {
            const int d = 1 << j;
            const float g = __ldg(&gp[j]);
            const int s3 = n - 3 * d, s2 = n - 2 * d, s1 = n - d;
            if (s3 >= 0) acc = fmaf(g * D4_0, slab[s3 * 16 + hd], acc);
            if (s2 >= 0) acc = fmaf(g * D4_1, slab[s2 * 16 + hd], acc);
            if (s1 >= 0) acc = fmaf(g * D4_2, slab[s1 * 16 + hd], acc);
        }
        g_outf[((size_t)bh * N_ + n) * HD_ + hd0 + hd] = acc;
    }
}

// -------- stage: head coupling + gate; emits fp16 hi/lo of G ------------------
__global__ __launch_bounds__(256)
void couple_gate_kernel(const float* __restrict__ fc)
{
    __shared__ float sf[H_ * HD_];
    __shared__ float cp[H_][H_];

    const int bn = blockIdx.x;
    const int b  = bn >> 11;
    const int n  = bn & (N_ - 1);
    const int tid = threadIdx.x;

#pragma unroll
    for (int r = 0; r < 4; r++) {
        const int idx = tid + r * 256;
        sf[idx] = g_outf[(((size_t)(b * H_ + (idx >> 6))) * N_ + n) * HD_ + (idx & 63)];
    }
    if (tid < H_) {
        float row[H_];
        float mx = -1e30f;
#pragma unroll
        for (int j = 0; j < H_; j++) { row[j] = fc[tid * H_ + j]; mx = fmaxf(mx, row[j]); }
        float sum = 0.f;
#pragma unroll
        for (int j = 0; j < H_; j++) { row[j] = __expf(row[j] - mx); sum += row[j]; }
        const float inv = 1.f / sum;
#pragma unroll
        for (int j = 0; j < H_; j++) cp[tid][j] = row[j] * inv;
    }
    __syncthreads();

    const size_t grow = ((size_t)b * N_ + n) * D_;
#pragma unroll
    for (int r = 0; r < 4; r++) {
        const int idx = tid + r * 256;
        const int i = idx >> 6, hd = idx & 63;
        float acc = 0.f;
#pragma unroll
        for (int j = 0; j < H_; j++) acc = fmaf(cp[i][j], sf[j * HD_ + hd], acc);
        const float v = acc * g_gate[grow + idx];
        const __half h = __float2half(v);
        g_Ghi[grow + idx] = h;
        g_Glo[grow + idx] = __float2half(v - __half2float(h));
    }
}

// ------------------------------- launch --------------------------------------
extern "C" void kernel_launch(void* const* d_in, const int* in_sizes, int n_in,
                              void* d_out, int out_size)
{
    const float* x    = (const float*)d_in[0];
    const float* Wqkv = (const float*)d_in[1];
    const float* bqkv = (const float*)d_in[2];
    const float* Wo   = (const float*)d_in[3];
    const float* bo   = (const float*)d_in[4];
    const float* Wg   = (const float*)d_in[5];
    const float* bg   = (const float*)d_in[6];
    const float* scale_gain = (const float*)d_in[7];
    const float* Wqs  = (const float*)d_in[8];
    const float* fc   = (const float*)d_in[9];
    float* out = (float*)d_out;

    float *p_qkv, *p_gate, *p_logits;
    __half *p_xhi, *p_xlo, *p_Ghi, *p_Glo, *p_Wkvhi, *p_Wghi, *p_Wohi, *p_Weff;
    cudaGetSymbolAddress((void**)&p_qkv,  g_qkv);
    cudaGetSymbolAddress((void**)&p_gate, g_gate);
    cudaGetSymbolAddress((void**)&p_logits, g_logits);
    cudaGetSymbolAddress((void**)&p_xhi, g_xhi);   cudaGetSymbolAddress((void**)&p_xlo, g_xlo);
    cudaGetSymbolAddress((void**)&p_Ghi, g_Ghi);   cudaGetSymbolAddress((void**)&p_Glo, g_Glo);
    cudaGetSymbolAddress((void**)&p_Wkvhi, g_Wkvhi);
    cudaGetSymbolAddress((void**)&p_Wghi, g_Wghi);
    cudaGetSymbolAddress((void**)&p_Wohi, g_Wohi);
    cudaGetSymbolAddress((void**)&p_Weff, g_Weffhi);

    cudaFuncSetAttribute(gemm_1pass_combo,  cudaFuncAttributeMaxDynamicSharedMemorySize, NSTAGE * 2 * TILEB);
    cudaFuncSetAttribute(gemm_2pass<false>, cudaFuncAttributeMaxDynamicSharedMemorySize, NSTAGE * 3 * TILEB);
    cudaFuncSetAttribute(conv_kernel2, cudaFuncAttributeMaxDynamicSharedMemorySize, CONV_SMEM);

    // 0) splits + Weff precompute
    {
        int n4 = M_ * D_ / 4;
        split_kernel<<<(n4 + 255) / 256, 256>>>((const float4*)x,
            (__half2*)p_xhi, (__half2*)p_xlo, n4);
        n4 = 2 * D_ * D_ / 4;   // Wk, Wv rows of Wqkv
        splith_kernel<<<(n4 + 255) / 256, 256>>>((const float4*)(Wqkv + (size_t)D_ * D_),
            (__half2*)p_Wkvhi, n4);
        n4 = D_ * D_ / 4;
        splith_kernel<<<(n4 + 255) / 256, 256>>>((const float4*)Wg, (__half2*)p_Wghi, n4);
        splith_kernel<<<(n4 + 255) / 256, 256>>>((const float4*)Wo, (__half2*)p_Wohi, n4);
        dim3 wgrid(D_ / 256, 256);
        weff_kernel<<<wgrid, 256>>>(Wqkv, Wqs, p_Weff);
    }

    // 1) combined 1-pass: k | gate | logits
    {
        dim3 grid(18, M_ / GBM);
        gemm_1pass_combo<<<grid, 256, NSTAGE * 2 * TILEB>>>(
            p_xhi, p_Wkvhi, p_Wghi, p_Weff,
            bqkv + D_, bg, p_qkv + D_, p_gate, p_logits);
    }
    // 2) v = x @ Wv^T + bv   (2-pass, x compensated)
    {
        dim3 grid(D_ / GBN, M_ / GBM);
        gemm_2pass<false><<<grid, 256, NSTAGE * 3 * TILEB>>>(
            p_xhi, p_xlo, p_Wkvhi + (size_t)D_ * D_,
            bqkv + 2 * D_, p_qkv + 2 * D_, 3 * D_, D_);
    }
    // 3) gains + field
    {
        const int totalWarps = B_ * H_ * N_;
        gains_field_kernel<<<totalWarps / 8, 8 * 32>>>(p_qkv, p_logits, scale_gain);
    }
    // 4) multiscale causal conv
    {
        dim3 grid(HD_ / 16, B_ * H_);
        conv_kernel2<<<grid, 512, CONV_SMEM>>>();
    }
    // 5) head coupling + gate (emits fp16 hi/lo of G)
    couple_gate_kernel<<<B_ * N_, 256>>>(fc);

    // 6) out = G @ Wo^T + bo   (2-pass, G compensated)
    {
        dim3 grid(D_ / GBN, M_ / GBM);
        gemm_2pass<false><<<grid, 256, NSTAGE * 3 * TILEB>>>(
            p_Ghi, p_Glo, p_Wohi, bo, out, D_, D_);
    }
}

// round 6
// speedup vs baseline: 3.9976x; 1.0238x over previous
#include <cuda_runtime.h>
#include <cuda_fp16.h>
#include <math.h>
#include <stdint.h>

// Problem dims (fixed by the reference)
#define B_    4
#define N_    2048
#define D_    1024
#define H_    16
#define HD_   64
#define S_    11
#define M_    (B_ * N_)   // 8192

#define D4_0 0.4829629131445341f
#define D4_1 0.8365163037378079f
#define D4_2 0.2241438680420134f
#define D4_3 (-0.1294095225512604f)

// ---------------- scratch (static device globals; no allocation) -------------
__device__ __align__(256) float g_gate[M_ * D_];
__device__ __align__(256) float g_logits[M_ * 256];     // h*11+s cols (176 used)
__device__ __align__(256) float g_kmag[M_ * H_];        // [m][h]
__device__ __align__(256) float g_field[B_ * H_ * N_ * HD_];   // [bh][n][hd]
__device__ __align__(256) float g_gains[B_ * H_ * N_ * S_];    // [bh][n][s]
__device__ __align__(256) float g_outf [M_ * D_];       // [b][n][h*64+hd]
__device__ __align__(256) float g_zerobias[256];

__device__ __align__(256) __half g_xhi[M_ * D_];
__device__ __align__(256) __half g_xlo[M_ * D_];
__device__ __align__(256) __half g_Ghi[M_ * D_];
__device__ __align__(256) __half g_Glo[M_ * D_];
__device__ __align__(256) __half g_Wkvhi[2 * D_ * D_];  // Wk, Wv hi
__device__ __align__(256) __half g_Wghi[D_ * D_];
__device__ __align__(256) __half g_Wohi[D_ * D_];
__device__ __align__(256) __half g_Weffhi[256 * D_];    // rows 176..255 zero

// ============================ PTX helpers ====================================
__device__ __forceinline__ uint32_t smem_u32(const void* p) {
    uint32_t a;
    asm("{ .reg .u64 t; cvta.to.shared.u64 t, %1; cvt.u32.u64 %0, t; }" : "=r"(a) : "l"(p));
    return a;
}

#define CP_ASYNC_16(sp, gp) \
    asm volatile("cp.async.cg.shared.global [%0], [%1], 16;" :: "r"(sp), "l"(gp) : "memory")
#define CP_COMMIT() asm volatile("cp.async.commit_group;" ::: "memory")
#define CP_WAIT(n)  asm volatile("cp.async.wait_group %0;" :: "n"(n) : "memory")

#define LDSM4(r0, r1, r2, r3, addr) \
    asm volatile("ldmatrix.sync.aligned.m8n8.x4.shared.b16 {%0,%1,%2,%3}, [%4];" \
        : "=r"(r0), "=r"(r1), "=r"(r2), "=r"(r3) : "r"(addr))
#define LDSM2(r0, r1, addr) \
    asm volatile("ldmatrix.sync.aligned.m8n8.x2.shared.b16 {%0,%1}, [%2];" \
        : "=r"(r0), "=r"(r1) : "r"(addr))

#define MMA16816(d, a, b) \
    asm volatile("mma.sync.aligned.m16n8k16.row.col.f32.f16.f16.f32 " \
        "{%0,%1,%2,%3}, {%4,%5,%6,%7}, {%8,%9}, {%0,%1,%2,%3};" \
        : "+f"((d)[0]), "+f"((d)[1]), "+f"((d)[2]), "+f"((d)[3]) \
        : "r"((a)[0]), "r"((a)[1]), "r"((a)[2]), "r"((a)[3]), "r"((b)[0]), "r"((b)[1]))

// ======================= fp16 tensor-core GEMM building blocks ===============
#define GBM 128
#define GBN 128
#define GBK 32
#define NSTAGE 4
#define ROWB   80
#define TILEB  (128 * ROWB)

// ---- 2-pass GEMM: (Ahi+Alo) @ Bhi^T + bias ----------------------------------
// FIELD=false: plain store to C (ldc).  FIELD=true: multiply by kmag[m][h] and
// scatter into g_field [bh][n][hd] layout.
template<bool FIELD>
__global__ __launch_bounds__(256, 1)
void gemm_2pass(const __half* __restrict__ Ahi, const __half* __restrict__ Alo,
                const __half* __restrict__ Bhi,
                const float* __restrict__ bias, float* __restrict__ C,
                const float* __restrict__ kmag, int ldc, int K)
{
    constexpr int STAGEB = 3 * TILEB;
    extern __shared__ char smx[];
    const uint32_t sbase = smem_u32(smx);
    const int t = threadIdx.x;
    const int wid = t >> 5, lane = t & 31;
    const int wm = wid & 3, wn = wid >> 2;
    const int m0 = blockIdx.y * GBM;
    const int n0 = blockIdx.x * GBN;
    const int KITERS = K / GBK;

    float acc[2][8][4];
#pragma unroll
    for (int mi = 0; mi < 2; mi++)
#pragma unroll
        for (int ni = 0; ni < 8; ni++)
#pragma unroll
            for (int v = 0; v < 4; v++) acc[mi][ni][v] = 0.f;

    auto load_stage = [&](int stage, int kk) {
        const uint32_t sb = sbase + stage * STAGEB;
        const int r = t >> 2, c = t & 3;
#pragma unroll
        for (int j = 0; j < 6; j++) {
            const int tile = j >> 1;
            const int row  = ((j & 1) << 6) + r;
            const __half* g;
            int grow;
            if (tile == 0)      { g = Ahi; grow = m0 + row; }
            else if (tile == 1) { g = Alo; grow = m0 + row; }
            else                { g = Bhi; grow = n0 + row; }
            CP_ASYNC_16(sb + tile * TILEB + row * ROWB + c * 16,
                        g + (size_t)grow * K + kk + c * 8);
        }
        CP_COMMIT();
    };

#pragma unroll
    for (int s = 0; s < NSTAGE - 1; s++) load_stage(s, s * GBK);

    const uint32_t a_off = (wm * 32 + (lane & 15)) * ROWB + (lane >> 4) * 16;
    const uint32_t b_off = (wn * 64 + (lane & 7)) * ROWB + ((lane >> 3) & 1) * 16;

    for (int it = 0; it < KITERS; it++) {
        CP_WAIT(NSTAGE - 2);
        __syncthreads();
        const int kload = it + NSTAGE - 1;
        if (kload < KITERS) load_stage(kload % NSTAGE, kload * GBK);

        const uint32_t st = sbase + (it % NSTAGE) * STAGEB;
#pragma unroll
        for (int ks = 0; ks < 2; ks++) {
            const uint32_t kb = ks * 32;
            uint32_t ah[2][4], al[2][4], bh[8][2];
#pragma unroll
            for (int mi = 0; mi < 2; mi++) {
                const uint32_t ar = st + a_off + mi * (16 * ROWB) + kb;
                LDSM4(ah[mi][0], ah[mi][1], ah[mi][2], ah[mi][3], ar);
                LDSM4(al[mi][0], al[mi][1], al[mi][2], al[mi][3], ar + TILEB);
            }
#pragma unroll
            for (int ni = 0; ni < 8; ni++) {
                const uint32_t br = st + 2 * TILEB + b_off + ni * (8 * ROWB) + kb;
                LDSM2(bh[ni][0], bh[ni][1], br);
            }
#pragma unroll
            for (int mi = 0; mi < 2; mi++)
#pragma unroll
                for (int ni = 0; ni < 8; ni++) {
                    MMA16816(acc[mi][ni], ah[mi], bh[ni]);
                    MMA16816(acc[mi][ni], al[mi], bh[ni]);
                }
        }
    }

    const int mrow = m0 + wm * 32 + (lane >> 2);
    const int ncol = n0 + wn * 64 + (lane & 3) * 2;

    if (FIELD) {
        const int head = (n0 >> 6) + wn;         // 64-col head within this block
        const int hdb  = (lane & 3) * 2;
#pragma unroll
        for (int mi = 0; mi < 2; mi++) {
            const int r0 = mrow + mi * 16;
            const int r1 = r0 + 8;
            const float km0 = __ldg(&kmag[(size_t)r0 * H_ + head]);
            const float km1 = __ldg(&kmag[(size_t)r1 * H_ + head]);
            float* f0 = g_field + (((size_t)((r0 >> 11) * H_ + head) * N_ + (r0 & (N_ - 1))) * HD_);
            float* f1 = g_field + (((size_t)((r1 >> 11) * H_ + head) * N_ + (r1 & (N_ - 1))) * HD_);
#pragma unroll
            for (int ni = 0; ni < 8; ni++) {
                const int hd = hdb + ni * 8;
                const int cg = head * 64 + hd;    // global col for bias
                const float b0 = __ldg(&bias[cg]);
                const float b1 = __ldg(&bias[cg + 1]);
                *(float2*)(f0 + hd) = make_float2((acc[mi][ni][0] + b0) * km0,
                                                  (acc[mi][ni][1] + b1) * km0);
                *(float2*)(f1 + hd) = make_float2((acc[mi][ni][2] + b0) * km1,
                                                  (acc[mi][ni][3] + b1) * km1);
            }
        }
    } else {
#pragma unroll
        for (int mi = 0; mi < 2; mi++)
#pragma unroll
            for (int ni = 0; ni < 8; ni++) {
                const int cbase = ncol + ni * 8;
                const float b0 = __ldg(&bias[cbase]);
                const float b1 = __ldg(&bias[cbase + 1]);
                const int r0 = mrow + mi * 16;
                *(float2*)(C + (size_t)r0 * ldc + cbase) =
                    make_float2(acc[mi][ni][0] + b0, acc[mi][ni][1] + b1);
                *(float2*)(C + (size_t)(r0 + 8) * ldc + cbase) =
                    make_float2(acc[mi][ni][2] + b0, acc[mi][ni][3] + b1);
            }
    }
}

// ---- combined 1-pass GEMM: kmag | gate | logits in one launch ---------------
// bx 0..7:  k = x@Wk^T + bk  -> reduce ||k|| per head -> g_kmag (k not stored)
// bx 8..15: gate = sigmoid(x@Wg^T + bg) -> g_gate
// bx 16..17: logits = x@Weff^T          -> g_logits
__global__ __launch_bounds__(256, 1)
void gemm_1pass_combo(const __half* __restrict__ xhi,
                      const __half* __restrict__ Wk,
                      const __half* __restrict__ Wg,
                      const __half* __restrict__ Weff,
                      const float* __restrict__ bk,
                      const float* __restrict__ bg,
                      float* __restrict__ Ckmag, float* __restrict__ Cgate,
                      float* __restrict__ Clog)
{
    constexpr int STAGEB = 2 * TILEB;
    constexpr int K = D_;
    extern __shared__ char smx[];
    const uint32_t sbase = smem_u32(smx);
    const int t = threadIdx.x;
    const int wid = t >> 5, lane = t & 31;
    const int wm = wid & 3, wn = wid >> 2;
    const int m0 = blockIdx.y * GBM;
    const int bx = blockIdx.x;

    const __half* Bp;
    const float* bias;
    int n0c;
    if (bx < 8)       { Bp = Wk   + (size_t)bx * 128 * K;        bias = bk;         n0c = bx * 128; }
    else if (bx < 16) { Bp = Wg   + (size_t)(bx - 8) * 128 * K;  bias = bg;         n0c = (bx - 8) * 128; }
    else              { Bp = Weff + (size_t)(bx - 16) * 128 * K; bias = g_zerobias; n0c = (bx - 16) * 128; }

    const int KITERS = K / GBK;

    float acc[2][8][4];
#pragma unroll
    for (int mi = 0; mi < 2; mi++)
#pragma unroll
        for (int ni = 0; ni < 8; ni++)
#pragma unroll
            for (int v = 0; v < 4; v++) acc[mi][ni][v] = 0.f;

    auto load_stage = [&](int stage, int kk) {
        const uint32_t sb = sbase + stage * STAGEB;
        const int r = t >> 2, c = t & 3;
#pragma unroll
        for (int j = 0; j < 4; j++) {
            const int tile = j >> 1;
            const int row  = ((j & 1) << 6) + r;
            const __half* g = (tile == 0) ? xhi : Bp;
            const int grow  = (tile == 0) ? (m0 + row) : row;
            CP_ASYNC_16(sb + tile * TILEB + row * ROWB + c * 16,
                        g + (size_t)grow * K + kk + c * 8);
        }
        CP_COMMIT();
    };

#pragma unroll
    for (int s = 0; s < NSTAGE - 1; s++) load_stage(s, s * GBK);

    const uint32_t a_off = (wm * 32 + (lane & 15)) * ROWB + (lane >> 4) * 16;
    const uint32_t b_off = (wn * 64 + (lane & 7)) * ROWB + ((lane >> 3) & 1) * 16;

    for (int it = 0; it < KITERS; it++) {
        CP_WAIT(NSTAGE - 2);
        __syncthreads();
        const int kload = it + NSTAGE - 1;
        if (kload < KITERS) load_stage(kload % NSTAGE, kload * GBK);

        const uint32_t st = sbase + (it % NSTAGE) * STAGEB;
#pragma unroll
        for (int ks = 0; ks < 2; ks++) {
            const uint32_t kb = ks * 32;
            uint32_t ah[2][4], bh[8][2];
#pragma unroll
            for (int mi = 0; mi < 2; mi++) {
                const uint32_t ar = st + a_off + mi * (16 * ROWB) + kb;
                LDSM4(ah[mi][0], ah[mi][1], ah[mi][2], ah[mi][3], ar);
            }
#pragma unroll
            for (int ni = 0; ni < 8; ni++) {
                const uint32_t br = st + TILEB + b_off + ni * (8 * ROWB) + kb;
                LDSM2(bh[ni][0], bh[ni][1], br);
            }
#pragma unroll
            for (int mi = 0; mi < 2; mi++)
#pragma unroll
                for (int ni = 0; ni < 8; ni++)
                    MMA16816(acc[mi][ni], ah[mi], bh[ni]);
        }
    }

    const int mrow = m0 + wm * 32 + (lane >> 2);
    const int ncl  = wn * 64 + (lane & 3) * 2;

    if (bx < 8) {
        // ||k|| per (row, head): this block's 128 cols are heads 2bx, 2bx+1;
        // wn selects the head. Reduce sum of squares across the lane quad.
        float rs[2][2] = {{0.f, 0.f}, {0.f, 0.f}};
#pragma unroll
        for (int mi = 0; mi < 2; mi++)
#pragma unroll
            for (int ni = 0; ni < 8; ni++) {
                const int cl = n0c + ncl + ni * 8;
                const float b0 = __ldg(&bias[cl]);
                const float b1 = __ldg(&bias[cl + 1]);
                const float v0 = acc[mi][ni][0] + b0, v1 = acc[mi][ni][1] + b1;
                const float v2 = acc[mi][ni][2] + b0, v3 = acc[mi][ni][3] + b1;
                rs[mi][0] += v0 * v0 + v1 * v1;
                rs[mi][1] += v2 * v2 + v3 * v3;
            }
#pragma unroll
        for (int mi = 0; mi < 2; mi++)
#pragma unroll
            for (int hf = 0; hf < 2; hf++) {
                rs[mi][hf] += __shfl_xor_sync(0xffffffffu, rs[mi][hf], 1);
                rs[mi][hf] += __shfl_xor_sync(0xffffffffu, rs[mi][hf], 2);
            }
        if ((lane & 3) == 0) {
            const int head = bx * 2 + wn;
#pragma unroll
            for (int mi = 0; mi < 2; mi++) {
                const int r0 = mrow + mi * 16;
                Ckmag[(size_t)r0 * H_ + head]       = sqrtf(rs[mi][0]);
                Ckmag[(size_t)(r0 + 8) * H_ + head] = sqrtf(rs[mi][1]);
            }
        }
    } else {
        float* C  = (bx < 16) ? Cgate : Clog;
        const int ldc = (bx < 16) ? D_ : 256;
        const bool sig = (bx < 16);
#pragma unroll
        for (int mi = 0; mi < 2; mi++)
#pragma unroll
            for (int ni = 0; ni < 8; ni++) {
                const int cl = n0c + ncl + ni * 8;
                const float b0 = __ldg(&bias[cl]);
                const float b1 = __ldg(&bias[cl + 1]);
                float v0 = acc[mi][ni][0] + b0, v1 = acc[mi][ni][1] + b1;
                float v2 = acc[mi][ni][2] + b0, v3 = acc[mi][ni][3] + b1;
                if (sig) {
                    v0 = 1.f / (1.f + __expf(-v0)); v1 = 1.f / (1.f + __expf(-v1));
                    v2 = 1.f / (1.f + __expf(-v2)); v3 = 1.f / (1.f + __expf(-v3));
                }
                const int r0 = mrow + mi * 16;
                *(float2*)(C + (size_t)r0 * ldc + cl)       = make_float2(v0, v1);
                *(float2*)(C + (size_t)(r0 + 8) * ldc + cl) = make_float2(v2, v3);
            }
    }
}

// ---------------- splits ------------------------------------------------------
__global__ __launch_bounds__(256)
void split_kernel(const float4* __restrict__ src, __half2* __restrict__ hi,
                  __half2* __restrict__ lo, int n4)
{
    const int i = blockIdx.x * blockDim.x + threadIdx.x;
    if (i >= n4) return;
    const float4 v = src[i];
    const __half h0 = __float2half(v.x), h1 = __float2half(v.y);
    const __half h2 = __float2half(v.z), h3 = __float2half(v.w);
    hi[2 * i]     = __halves2half2(h0, h1);
    hi[2 * i + 1] = __halves2half2(h2, h3);
    lo[2 * i]     = __halves2half2(__float2half(v.x - __half2float(h0)),
                                   __float2half(v.y - __half2float(h1)));
    lo[2 * i + 1] = __halves2half2(__float2half(v.z - __half2float(h2)),
                                   __float2half(v.w - __half2float(h3)));
}

__global__ __launch_bounds__(256)
void splith_kernel(const float4* __restrict__ src, __half2* __restrict__ hi, int n4)
{
    const int i = blockIdx.x * blockDim.x + threadIdx.x;
    if (i >= n4) return;
    const float4 v = src[i];
    hi[2 * i]     = __halves2half2(__float2half(v.x), __float2half(v.y));
    hi[2 * i + 1] = __halves2half2(__float2half(v.z), __float2half(v.w));
}

// ---------------- Weff = Wqs @ Wq (per head), fp32 -> fp16 --------------------
__global__ __launch_bounds__(256)
void weff_kernel(const float* __restrict__ Wqkv, const float* __restrict__ Wqs,
                 __half* __restrict__ Weff)
{
    const int r = blockIdx.y;
    const int k = blockIdx.x * 256 + threadIdx.x;
    float acc = 0.f;
    if (r < 176) {
        const int h = r / 11, s = r % 11;
        const float* wq = Wqkv + (size_t)(h * 64) * D_ + k;
        const float* ws = Wqs + s * HD_;
#pragma unroll 16
        for (int d = 0; d < 64; d++)
            acc = fmaf(__ldg(&ws[d]), __ldg(&wq[(size_t)d * D_]), acc);
    }
    Weff[(size_t)r * D_ + k] = __float2half(acc);
    if (r == 0 && blockIdx.x == 0) g_zerobias[threadIdx.x] = 0.f;
}

// -------- gains: softmax over S logits per (m, h) -----------------------------
__global__ __launch_bounds__(256)
void gains_kernel(const float* __restrict__ logits,
                  const float* __restrict__ scale_gain)
{
    const int idx = blockIdx.x * 256 + threadIdx.x;   // 0 .. M*H-1
    const int m = idx >> 4, h = idx & 15;
    const float* lp = logits + (size_t)m * 256 + h * S_;

    float l[S_];
    float mx = -1e30f;
#pragma unroll
    for (int s = 0; s < S_; s++) {
        l[s] = __ldg(&lp[s]) + __ldg(&scale_gain[s * H_ + h]);
        mx = fmaxf(mx, l[s]);
    }
    float sum = 0.f;
#pragma unroll
    for (int s = 0; s < S_; s++) { l[s] = __expf(l[s] - mx); sum += l[s]; }
    const float inv = 1.f / sum;

    float* gp = g_gains + ((size_t)((m >> 11) * H_ + h) * N_ + (m & (N_ - 1))) * S_;
#pragma unroll
    for (int s = 0; s < S_; s++) gp[s] = l[s] * inv;
}

// -------- stage: causal multiscale dilated D4 conv (smem-slab) ----------------
// writes outf in [b][n][h*64+hd] layout for coalesced couple_gate loads
#define CONV_SMEM (N_ * 16 * 4)   // 131072 B

__global__ __launch_bounds__(512)
void conv_kernel2()
{
    extern __shared__ float slab[];          // [2048][16]
    const int bh  = blockIdx.y;
    const int hd0 = blockIdx.x * 16;
    const int t   = threadIdx.x;
    const int b   = bh >> 4, h = bh & 15;

    const float* fb = g_field + (size_t)bh * N_ * HD_;
#pragma unroll
    for (int i = 0; i < 16; i++) {
        const int idx = i * 512 + t;
        const int n = idx >> 2, c = idx & 3;
        ((float4*)slab)[idx] = *(const float4*)(fb + (size_t)n * HD_ + hd0 + c * 4);
    }
    __syncthreads();

    const int hd = t & 15, nb = t >> 4;
    float* ob = g_outf + (size_t)b * N_ * D_ + h * HD_ + hd0 + hd;
    for (int ni = 0; ni < 64; ni++) {
        const int n = ni * 32 + nb;
        const float* gp = g_gains + ((size_t)bh * N_ + n) * S_;

        float acc = D4_3 * slab[n * 16 + hd];
#pragma unroll
        for (int j = 0; j < S_; j++) {
            const int d = 1 << j;
            const float g = __ldg(&gp[j]);
            const int s3 = n - 3 * d, s2 = n - 2 * d, s1 = n - d;
            if (s3 >= 0) acc = fmaf(g * D4_0, slab[s3 * 16 + hd], acc);
            if (s2 >= 0) acc = fmaf(g * D4_1, slab[s2 * 16 + hd], acc);
            if (s1 >= 0) acc = fmaf(g * D4_2, slab[s1 * 16 + hd], acc);
        }
        ob[(size_t)n * D_] = acc;
    }
}

// -------- stage: head coupling + gate; emits fp16 hi/lo of G ------------------
__global__ __launch_bounds__(256)
void couple_gate_kernel(const float* __restrict__ fc)
{
    __shared__ float sf[D_];
    __shared__ float cp[H_][H_];

    const int bn = blockIdx.x;            // b*2048 + n
    const int tid = threadIdx.x;

    const float* orow = g_outf + (size_t)bn * D_;
#pragma unroll
    for (int r = 0; r < 1; r++)
        ((float4*)sf)[tid] = ((const float4*)orow)[tid];
    if (tid < H_) {
        float row[H_];
        float mx = -1e30f;
#pragma unroll
        for (int j = 0; j < H_; j++) { row[j] = fc[tid * H_ + j]; mx = fmaxf(mx, row[j]); }
        float sum = 0.f;
#pragma unroll
        for (int j = 0; j < H_; j++) { row[j] = __expf(row[j] - mx); sum += row[j]; }
        const float inv = 1.f / sum;
#pragma unroll
        for (int j = 0; j < H_; j++) cp[tid][j] = row[j] * inv;
    }
    __syncthreads();

    const size_t grow = (size_t)bn * D_;
#pragma unroll
    for (int r = 0; r < 4; r++) {
        const int idx = tid + r * 256;
        const int i = idx >> 6, hd = idx & 63;
        float acc = 0.f;
#pragma unroll
        for (int j = 0; j < H_; j++) acc = fmaf(cp[i][j], sf[j * HD_ + hd], acc);
        const float v = acc * g_gate[grow + idx];
        const __half h = __float2half(v);
        g_Ghi[grow + idx] = h;
        g_Glo[grow + idx] = __float2half(v - __half2float(h));
    }
}

// ------------------------------- launch --------------------------------------
extern "C" void kernel_launch(void* const* d_in, const int* in_sizes, int n_in,
                              void* d_out, int out_size)
{
    const float* x    = (const float*)d_in[0];
    const float* Wqkv = (const float*)d_in[1];
    const float* bqkv = (const float*)d_in[2];
    const float* Wo   = (const float*)d_in[3];
    const float* bo   = (const float*)d_in[4];
    const float* Wg   = (const float*)d_in[5];
    const float* bg   = (const float*)d_in[6];
    const float* scale_gain = (const float*)d_in[7];
    const float* Wqs  = (const float*)d_in[8];
    const float* fc   = (const float*)d_in[9];
    float* out = (float*)d_out;

    float *p_gate, *p_logits, *p_kmag;
    __half *p_xhi, *p_xlo, *p_Ghi, *p_Glo, *p_Wkvhi, *p_Wghi, *p_Wohi, *p_Weff;
    cudaGetSymbolAddress((void**)&p_gate, g_gate);
    cudaGetSymbolAddress((void**)&p_logits, g_logits);
    cudaGetSymbolAddress((void**)&p_kmag, g_kmag);
    cudaGetSymbolAddress((void**)&p_xhi, g_xhi);   cudaGetSymbolAddress((void**)&p_xlo, g_xlo);
    cudaGetSymbolAddress((void**)&p_Ghi, g_Ghi);   cudaGetSymbolAddress((void**)&p_Glo, g_Glo);
    cudaGetSymbolAddress((void**)&p_Wkvhi, g_Wkvhi);
    cudaGetSymbolAddress((void**)&p_Wghi, g_Wghi);
    cudaGetSymbolAddress((void**)&p_Wohi, g_Wohi);
    cudaGetSymbolAddress((void**)&p_Weff, g_Weffhi);

    cudaFuncSetAttribute(gemm_1pass_combo,  cudaFuncAttributeMaxDynamicSharedMemorySize, NSTAGE * 2 * TILEB);
    cudaFuncSetAttribute(gemm_2pass<false>, cudaFuncAttributeMaxDynamicSharedMemorySize, NSTAGE * 3 * TILEB);
    cudaFuncSetAttribute(gemm_2pass<true>,  cudaFuncAttributeMaxDynamicSharedMemorySize, NSTAGE * 3 * TILEB);
    cudaFuncSetAttribute(conv_kernel2, cudaFuncAttributeMaxDynamicSharedMemorySize, CONV_SMEM);

    // 0) splits + Weff precompute
    {
        int n4 = M_ * D_ / 4;
        split_kernel<<<(n4 + 255) / 256, 256>>>((const float4*)x,
            (__half2*)p_xhi, (__half2*)p_xlo, n4);
        n4 = 2 * D_ * D_ / 4;
        splith_kernel<<<(n4 + 255) / 256, 256>>>((const float4*)(Wqkv + (size_t)D_ * D_),
            (__half2*)p_Wkvhi, n4);
        n4 = D_ * D_ / 4;
        splith_kernel<<<(n4 + 255) / 256, 256>>>((const float4*)Wg, (__half2*)p_Wghi, n4);
        splith_kernel<<<(n4 + 255) / 256, 256>>>((const float4*)Wo, (__half2*)p_Wohi, n4);
        dim3 wgrid(D_ / 256, 256);
        weff_kernel<<<wgrid, 256>>>(Wqkv, Wqs, p_Weff);
    }

    // 1) combined 1-pass: kmag | gate | logits
    {
        dim3 grid(18, M_ / GBM);
        gemm_1pass_combo<<<grid, 256, NSTAGE * 2 * TILEB>>>(
            p_xhi, p_Wkvhi, p_Wghi, p_Weff,
            bqkv + D_, bg, p_kmag, p_gate, p_logits);
    }
    // 2) gains softmax
    gains_kernel<<<M_ * H_ / 256, 256>>>(p_logits, scale_gain);

    // 3) v-GEMM -> field = (x@Wv^T + bv) * kmag, written in [bh][n][hd]
    {
        dim3 grid(D_ / GBN, M_ / GBM);
        gemm_2pass<true><<<grid, 256, NSTAGE * 3 * TILEB>>>(
            p_xhi, p_xlo, p_Wkvhi + (size_t)D_ * D_,
            bqkv + 2 * D_, nullptr, p_kmag, 0, D_);
    }
    // 4) multiscale causal conv -> outf [b][n][D]
    {
        dim3 grid(HD_ / 16, B_ * H_);
        conv_kernel2<<<grid, 512, CONV_SMEM>>>();
    }
    // 5) head coupling + gate (emits fp16 hi/lo of G)
    couple_gate_kernel<<<B_ * N_, 256>>>(fc);

    // 6) out = G @ Wo^T + bo   (2-pass, G compensated)
    {
        dim3 grid(D_ / GBN, M_ / GBM);
        gemm_2pass<false><<<grid, 256, NSTAGE * 3 * TILEB>>>(
            p_Ghi, p_Glo, p_Wohi, bo, out, nullptr, D_, D_);
    }
}

// round 7
// speedup vs baseline: 4.1249x; 1.0318x over previous
#include <cuda_runtime.h>
#include <cuda_fp16.h>
#include <math.h>
#include <stdint.h>

// Problem dims (fixed by the reference)
#define B_    4
#define N_    2048
#define D_    1024
#define H_    16
#define HD_   64
#define S_    11
#define M_    (B_ * N_)   // 8192

#define D4_0 0.4829629131445341f
#define D4_1 0.8365163037378079f
#define D4_2 0.2241438680420134f
#define D4_3 (-0.1294095225512604f)

// ---------------- scratch (static device globals; no allocation) -------------
__device__ __align__(256) __half g_gate[M_ * D_];
__device__ __align__(256) float g_logits[M_ * 256];     // h*11+s cols (176 used)
__device__ __align__(256) float g_kmag[M_ * H_];        // [m][h]
__device__ __align__(256) float g_field[B_ * H_ * N_ * HD_];   // [bh][n][hd]
__device__ __align__(256) float g_gains[B_ * H_ * N_ * S_];    // [bh][n][s]
__device__ __align__(256) __half g_outf [M_ * D_];      // [b][n][h*64+hd]
__device__ __align__(256) float g_zerobias[256];

__device__ __align__(256) __half g_xhi[M_ * D_];
__device__ __align__(256) __half g_xlo[M_ * D_];
__device__ __align__(256) __half g_Ghi[M_ * D_];
__device__ __align__(256) __half g_Glo[M_ * D_];
__device__ __align__(256) __half g_Wkvhi[2 * D_ * D_];  // Wk, Wv hi
__device__ __align__(256) __half g_Wghi[D_ * D_];
__device__ __align__(256) __half g_Wohi[D_ * D_];
__device__ __align__(256) __half g_Weffhi[256 * D_];    // rows 176..255 zero

// ============================ PTX helpers ====================================
__device__ __forceinline__ uint32_t smem_u32(const void* p) {
    uint32_t a;
    asm("{ .reg .u64 t; cvta.to.shared.u64 t, %1; cvt.u32.u64 %0, t; }" : "=r"(a) : "l"(p));
    return a;
}

#define CP_ASYNC_16(sp, gp) \
    asm volatile("cp.async.cg.shared.global [%0], [%1], 16;" :: "r"(sp), "l"(gp) : "memory")
#define CP_COMMIT() asm volatile("cp.async.commit_group;" ::: "memory")
#define CP_WAIT(n)  asm volatile("cp.async.wait_group %0;" :: "n"(n) : "memory")

#define LDSM4(r0, r1, r2, r3, addr) \
    asm volatile("ldmatrix.sync.aligned.m8n8.x4.shared.b16 {%0,%1,%2,%3}, [%4];" \
        : "=r"(r0), "=r"(r1), "=r"(r2), "=r"(r3) : "r"(addr))
#define LDSM2(r0, r1, addr) \
    asm volatile("ldmatrix.sync.aligned.m8n8.x2.shared.b16 {%0,%1}, [%2];" \
        : "=r"(r0), "=r"(r1) : "r"(addr))

#define MMA16816(d, a, b) \
    asm volatile("mma.sync.aligned.m16n8k16.row.col.f32.f16.f16.f32 " \
        "{%0,%1,%2,%3}, {%4,%5,%6,%7}, {%8,%9}, {%0,%1,%2,%3};" \
        : "+f"((d)[0]), "+f"((d)[1]), "+f"((d)[2]), "+f"((d)[3]) \
        : "r"((a)[0]), "r"((a)[1]), "r"((a)[2]), "r"((a)[3]), "r"((b)[0]), "r"((b)[1]))

// ======================= fp16 tensor-core GEMM building blocks ===============
#define GBM 128
#define GBN 128
#define GBK 32
#define NSTAGE 4
#define ROWB   80
#define TILEB  (128 * ROWB)

// ---- 2-pass GEMM: (Ahi+Alo) @ Bhi^T + bias ----------------------------------
// FIELD=false: plain fp32 store to C (ldc).  FIELD=true: multiply by kmag[m][h]
// and scatter into g_field [bh][n][hd] layout.
template<bool FIELD>
__global__ __launch_bounds__(256, 1)
void gemm_2pass(const __half* __restrict__ Ahi, const __half* __restrict__ Alo,
                const __half* __restrict__ Bhi,
                const float* __restrict__ bias, float* __restrict__ C,
                const float* __restrict__ kmag, int ldc, int K)
{
    constexpr int STAGEB = 3 * TILEB;
    extern __shared__ char smx[];
    const uint32_t sbase = smem_u32(smx);
    const int t = threadIdx.x;
    const int wid = t >> 5, lane = t & 31;
    const int wm = wid & 3, wn = wid >> 2;
    const int m0 = blockIdx.y * GBM;
    const int n0 = blockIdx.x * GBN;
    const int KITERS = K / GBK;

    float acc[2][8][4];
#pragma unroll
    for (int mi = 0; mi < 2; mi++)
#pragma unroll
        for (int ni = 0; ni < 8; ni++)
#pragma unroll
            for (int v = 0; v < 4; v++) acc[mi][ni][v] = 0.f;

    auto load_stage = [&](int stage, int kk) {
        const uint32_t sb = sbase + stage * STAGEB;
        const int r = t >> 2, c = t & 3;
#pragma unroll
        for (int j = 0; j < 6; j++) {
            const int tile = j >> 1;
            const int row  = ((j & 1) << 6) + r;
            const __half* g;
            int grow;
            if (tile == 0)      { g = Ahi; grow = m0 + row; }
            else if (tile == 1) { g = Alo; grow = m0 + row; }
            else                { g = Bhi; grow = n0 + row; }
            CP_ASYNC_16(sb + tile * TILEB + row * ROWB + c * 16,
                        g + (size_t)grow * K + kk + c * 8);
        }
        CP_COMMIT();
    };

#pragma unroll
    for (int s = 0; s < NSTAGE - 1; s++) load_stage(s, s * GBK);

    const uint32_t a_off = (wm * 32 + (lane & 15)) * ROWB + (lane >> 4) * 16;
    const uint32_t b_off = (wn * 64 + (lane & 7)) * ROWB + ((lane >> 3) & 1) * 16;

    for (int it = 0; it < KITERS; it++) {
        CP_WAIT(NSTAGE - 2);
        __syncthreads();
        const int kload = it + NSTAGE - 1;
        if (kload < KITERS) load_stage(kload % NSTAGE, kload * GBK);

        const uint32_t st = sbase + (it % NSTAGE) * STAGEB;
#pragma unroll
        for (int ks = 0; ks < 2; ks++) {
            const uint32_t kb = ks * 32;
            uint32_t ah[2][4], al[2][4], bh[8][2];
#pragma unroll
            for (int mi = 0; mi < 2; mi++) {
                const uint32_t ar = st + a_off + mi * (16 * ROWB) + kb;
                LDSM4(ah[mi][0], ah[mi][1], ah[mi][2], ah[mi][3], ar);
                LDSM4(al[mi][0], al[mi][1], al[mi][2], al[mi][3], ar + TILEB);
            }
#pragma unroll
            for (int ni = 0; ni < 8; ni++) {
                const uint32_t br = st + 2 * TILEB + b_off + ni * (8 * ROWB) + kb;
                LDSM2(bh[ni][0], bh[ni][1], br);
            }
            // pass-separated sweeps: 16 independent accumulators between
            // touches of the same acc -> no RAW pipeline bubbles
#pragma unroll
            for (int mi = 0; mi < 2; mi++)
#pragma unroll
                for (int ni = 0; ni < 8; ni++)
                    MMA16816(acc[mi][ni], ah[mi], bh[ni]);
#pragma unroll
            for (int mi = 0; mi < 2; mi++)
#pragma unroll
                for (int ni = 0; ni < 8; ni++)
                    MMA16816(acc[mi][ni], al[mi], bh[ni]);
        }
    }

    const int mrow = m0 + wm * 32 + (lane >> 2);
    const int ncol = n0 + wn * 64 + (lane & 3) * 2;

    if (FIELD) {
        const int head = (n0 >> 6) + wn;
        const int hdb  = (lane & 3) * 2;
#pragma unroll
        for (int mi = 0; mi < 2; mi++) {
            const int r0 = mrow + mi * 16;
            const int r1 = r0 + 8;
            const float km0 = __ldg(&kmag[(size_t)r0 * H_ + head]);
            const float km1 = __ldg(&kmag[(size_t)r1 * H_ + head]);
            float* f0 = g_field + (((size_t)((r0 >> 11) * H_ + head) * N_ + (r0 & (N_ - 1))) * HD_);
            float* f1 = g_field + (((size_t)((r1 >> 11) * H_ + head) * N_ + (r1 & (N_ - 1))) * HD_);
#pragma unroll
            for (int ni = 0; ni < 8; ni++) {
                const int hd = hdb + ni * 8;
                const int cg = head * 64 + hd;
                const float b0 = __ldg(&bias[cg]);
                const float b1 = __ldg(&bias[cg + 1]);
                *(float2*)(f0 + hd) = make_float2((acc[mi][ni][0] + b0) * km0,
                                                  (acc[mi][ni][1] + b1) * km0);
                *(float2*)(f1 + hd) = make_float2((acc[mi][ni][2] + b0) * km1,
                                                  (acc[mi][ni][3] + b1) * km1);
            }
        }
    } else {
#pragma unroll
        for (int mi = 0; mi < 2; mi++)
#pragma unroll
            for (int ni = 0; ni < 8; ni++) {
                const int cbase = ncol + ni * 8;
                const float b0 = __ldg(&bias[cbase]);
                const float b1 = __ldg(&bias[cbase + 1]);
                const int r0 = mrow + mi * 16;
                *(float2*)(C + (size_t)r0 * ldc + cbase) =
                    make_float2(acc[mi][ni][0] + b0, acc[mi][ni][1] + b1);
                *(float2*)(C + (size_t)(r0 + 8) * ldc + cbase) =
                    make_float2(acc[mi][ni][2] + b0, acc[mi][ni][3] + b1);
            }
    }
}

// ---- combined 1-pass GEMM: kmag | gate | logits in one launch ---------------
__global__ __launch_bounds__(256, 1)
void gemm_1pass_combo(const __half* __restrict__ xhi,
                      const __half* __restrict__ Wk,
                      const __half* __restrict__ Wg,
                      const __half* __restrict__ Weff,
                      const float* __restrict__ bk,
                      const float* __restrict__ bg,
                      float* __restrict__ Ckmag, __half* __restrict__ Cgate,
                      float* __restrict__ Clog)
{
    constexpr int STAGEB = 2 * TILEB;
    constexpr int K = D_;
    extern __shared__ char smx[];
    const uint32_t sbase = smem_u32(smx);
    const int t = threadIdx.x;
    const int wid = t >> 5, lane = t & 31;
    const int wm = wid & 3, wn = wid >> 2;
    const int m0 = blockIdx.y * GBM;
    const int bx = blockIdx.x;

    const __half* Bp;
    const float* bias;
    int n0c;
    if (bx < 8)       { Bp = Wk   + (size_t)bx * 128 * K;        bias = bk;         n0c = bx * 128; }
    else if (bx < 16) { Bp = Wg   + (size_t)(bx - 8) * 128 * K;  bias = bg;         n0c = (bx - 8) * 128; }
    else              { Bp = Weff + (size_t)(bx - 16) * 128 * K; bias = g_zerobias; n0c = (bx - 16) * 128; }

    const int KITERS = K / GBK;

    float acc[2][8][4];
#pragma unroll
    for (int mi = 0; mi < 2; mi++)
#pragma unroll
        for (int ni = 0; ni < 8; ni++)
#pragma unroll
            for (int v = 0; v < 4; v++) acc[mi][ni][v] = 0.f;

    auto load_stage = [&](int stage, int kk) {
        const uint32_t sb = sbase + stage * STAGEB;
        const int r = t >> 2, c = t & 3;
#pragma unroll
        for (int j = 0; j < 4; j++) {
            const int tile = j >> 1;
            const int row  = ((j & 1) << 6) + r;
            const __half* g = (tile == 0) ? xhi : Bp;
            const int grow  = (tile == 0) ? (m0 + row) : row;
            CP_ASYNC_16(sb + tile * TILEB + row * ROWB + c * 16,
                        g + (size_t)grow * K + kk + c * 8);
        }
        CP_COMMIT();
    };

#pragma unroll
    for (int s = 0; s < NSTAGE - 1; s++) load_stage(s, s * GBK);

    const uint32_t a_off = (wm * 32 + (lane & 15)) * ROWB + (lane >> 4) * 16;
    const uint32_t b_off = (wn * 64 + (lane & 7)) * ROWB + ((lane >> 3) & 1) * 16;

    for (int it = 0; it < KITERS; it++) {
        CP_WAIT(NSTAGE - 2);
        __syncthreads();
        const int kload = it + NSTAGE - 1;
        if (kload < KITERS) load_stage(kload % NSTAGE, kload * GBK);

        const uint32_t st = sbase + (it % NSTAGE) * STAGEB;
#pragma unroll
        for (int ks = 0; ks < 2; ks++) {
            const uint32_t kb = ks * 32;
            uint32_t ah[2][4], bh[8][2];
#pragma unroll
            for (int mi = 0; mi < 2; mi++) {
                const uint32_t ar = st + a_off + mi * (16 * ROWB) + kb;
                LDSM4(ah[mi][0], ah[mi][1], ah[mi][2], ah[mi][3], ar);
            }
#pragma unroll
            for (int ni = 0; ni < 8; ni++) {
                const uint32_t br = st + TILEB + b_off + ni * (8 * ROWB) + kb;
                LDSM2(bh[ni][0], bh[ni][1], br);
            }
#pragma unroll
            for (int mi = 0; mi < 2; mi++)
#pragma unroll
                for (int ni = 0; ni < 8; ni++)
                    MMA16816(acc[mi][ni], ah[mi], bh[ni]);
        }
    }

    const int mrow = m0 + wm * 32 + (lane >> 2);
    const int ncl  = wn * 64 + (lane & 3) * 2;

    if (bx < 8) {
        float rs[2][2] = {{0.f, 0.f}, {0.f, 0.f}};
#pragma unroll
        for (int mi = 0; mi < 2; mi++)
#pragma unroll
            for (int ni = 0; ni < 8; ni++) {
                const int cl = n0c + ncl + ni * 8;
                const float b0 = __ldg(&bias[cl]);
                const float b1 = __ldg(&bias[cl + 1]);
                const float v0 = acc[mi][ni][0] + b0, v1 = acc[mi][ni][1] + b1;
                const float v2 = acc[mi][ni][2] + b0, v3 = acc[mi][ni][3] + b1;
                rs[mi][0] += v0 * v0 + v1 * v1;
                rs[mi][1] += v2 * v2 + v3 * v3;
            }
#pragma unroll
        for (int mi = 0; mi < 2; mi++)
#pragma unroll
            for (int hf = 0; hf < 2; hf++) {
                rs[mi][hf] += __shfl_xor_sync(0xffffffffu, rs[mi][hf], 1);
                rs[mi][hf] += __shfl_xor_sync(0xffffffffu, rs[mi][hf], 2);
            }
        if ((lane & 3) == 0) {
            const int head = bx * 2 + wn;
#pragma unroll
            for (int mi = 0; mi < 2; mi++) {
                const int r0 = mrow + mi * 16;
                Ckmag[(size_t)r0 * H_ + head]       = sqrtf(rs[mi][0]);
                Ckmag[(size_t)(r0 + 8) * H_ + head] = sqrtf(rs[mi][1]);
            }
        }
    } else if (bx < 16) {
#pragma unroll
        for (int mi = 0; mi < 2; mi++)
#pragma unroll
            for (int ni = 0; ni < 8; ni++) {
                const int cl = n0c + ncl + ni * 8;
                const float b0 = __ldg(&bias[cl]);
                const float b1 = __ldg(&bias[cl + 1]);
                float v0 = acc[mi][ni][0] + b0, v1 = acc[mi][ni][1] + b1;
                float v2 = acc[mi][ni][2] + b0, v3 = acc[mi][ni][3] + b1;
                v0 = 1.f / (1.f + __expf(-v0)); v1 = 1.f / (1.f + __expf(-v1));
                v2 = 1.f / (1.f + __expf(-v2)); v3 = 1.f / (1.f + __expf(-v3));
                const int r0 = mrow + mi * 16;
                *(__half2*)(Cgate + (size_t)r0 * D_ + cl)       = __floats2half2_rn(v0, v1);
                *(__half2*)(Cgate + (size_t)(r0 + 8) * D_ + cl) = __floats2half2_rn(v2, v3);
            }
    } else {
#pragma unroll
        for (int mi = 0; mi < 2; mi++)
#pragma unroll
            for (int ni = 0; ni < 8; ni++) {
                const int cl = n0c + ncl + ni * 8;
                const int r0 = mrow + mi * 16;
                *(float2*)(Clog + (size_t)r0 * 256 + cl) =
                    make_float2(acc[mi][ni][0], acc[mi][ni][1]);
                *(float2*)(Clog + (size_t)(r0 + 8) * 256 + cl) =
                    make_float2(acc[mi][ni][2], acc[mi][ni][3]);
            }
    }
}

// ---------------- fused splits: one launch for x(hi/lo) + Wkv/Wg/Wo (hi) -----
// ranges (in float4 units):
//   [0, 2M)            x -> xhi + xlo
//   [2M, 2.5M)         Wkv rows of Wqkv -> Wkvhi
//   [2.5M, 2.75M)      Wg -> Wghi
//   [2.75M, 3M)        Wo -> Wohi
#define SPLIT_X   (M_ * D_ / 4)
#define SPLIT_KV  (2 * D_ * D_ / 4)
#define SPLIT_W   (D_ * D_ / 4)
#define SPLIT_TOT (SPLIT_X + SPLIT_KV + 2 * SPLIT_W)

__global__ __launch_bounds__(256)
void fused_split_kernel(const float4* __restrict__ x, const float4* __restrict__ Wkv,
                        const float4* __restrict__ Wg, const float4* __restrict__ Wo)
{
    const int i = blockIdx.x * blockDim.x + threadIdx.x;
    if (i >= SPLIT_TOT) return;
    if (i < SPLIT_X) {
        const float4 v = x[i];
        const __half h0 = __float2half(v.x), h1 = __float2half(v.y);
        const __half h2 = __float2half(v.z), h3 = __float2half(v.w);
        __half2* hi = (__half2*)g_xhi;
        __half2* lo = (__half2*)g_xlo;
        hi[2 * i]     = __halves2half2(h0, h1);
        hi[2 * i + 1] = __halves2half2(h2, h3);
        lo[2 * i]     = __halves2half2(__float2half(v.x - __half2float(h0)),
                                       __float2half(v.y - __half2float(h1)));
        lo[2 * i + 1] = __halves2half2(__float2half(v.z - __half2float(h2)),
                                       __float2half(v.w - __half2float(h3)));
        return;
    }
    const float4* src;
    __half2* dst;
    int j;
    if (i < SPLIT_X + SPLIT_KV)              { j = i - SPLIT_X;              src = Wkv; dst = (__half2*)g_Wkvhi; }
    else if (i < SPLIT_X + SPLIT_KV + SPLIT_W){ j = i - SPLIT_X - SPLIT_KV;   src = Wg;  dst = (__half2*)g_Wghi; }
    else                                      { j = i - SPLIT_X - SPLIT_KV - SPLIT_W; src = Wo; dst = (__half2*)g_Wohi; }
    const float4 v = src[j];
    dst[2 * j]     = __halves2half2(__float2half(v.x), __float2half(v.y));
    dst[2 * j + 1] = __halves2half2(__float2half(v.z), __float2half(v.w));
}

// ---------------- Weff = Wqs @ Wq (per head), fp32 -> fp16 --------------------
__global__ __launch_bounds__(256)
void weff_kernel(const float* __restrict__ Wqkv, const float* __restrict__ Wqs,
                 __half* __restrict__ Weff)
{
    const int r = blockIdx.y;
    const int k = blockIdx.x * 256 + threadIdx.x;
    float acc = 0.f;
    if (r < 176) {
        const int h = r / 11, s = r % 11;
        const float* wq = Wqkv + (size_t)(h * 64) * D_ + k;
        const float* ws = Wqs + s * HD_;
#pragma unroll 16
        for (int d = 0; d < 64; d++)
            acc = fmaf(__ldg(&ws[d]), __ldg(&wq[(size_t)d * D_]), acc);
    }
    Weff[(size_t)r * D_ + k] = __float2half(acc);
    if (r == 0 && blockIdx.x == 0) g_zerobias[threadIdx.x] = 0.f;
}

// -------- gains: softmax over S logits per (m, h) -----------------------------
__global__ __launch_bounds__(256)
void gains_kernel(const float* __restrict__ logits,
                  const float* __restrict__ scale_gain)
{
    const int idx = blockIdx.x * 256 + threadIdx.x;
    const int m = idx >> 4, h = idx & 15;
    const float* lp = logits + (size_t)m * 256 + h * S_;

    float l[S_];
    float mx = -1e30f;
#pragma unroll
    for (int s = 0; s < S_; s++) {
        l[s] = __ldg(&lp[s]) + __ldg(&scale_gain[s * H_ + h]);
        mx = fmaxf(mx, l[s]);
    }
    float sum = 0.f;
#pragma unroll
    for (int s = 0; s < S_; s++) { l[s] = __expf(l[s] - mx); sum += l[s]; }
    const float inv = 1.f / sum;

    float* gp = g_gains + ((size_t)((m >> 11) * H_ + h) * N_ + (m & (N_ - 1))) * S_;
#pragma unroll
    for (int s = 0; s < S_; s++) gp[s] = l[s] * inv;
}

// -------- stage: causal multiscale dilated D4 conv (smem-slab) ----------------
#define CONV_SMEM (N_ * 16 * 4)   // 131072 B

__global__ __launch_bounds__(512)
void conv_kernel2()
{
    extern __shared__ float slab[];          // [2048][16]
    const int bh  = blockIdx.y;
    const int hd0 = blockIdx.x * 16;
    const int t   = threadIdx.x;
    const int b   = bh >> 4, h = bh & 15;

    const float* fb = g_field + (size_t)bh * N_ * HD_;
#pragma unroll
    for (int i = 0; i < 16; i++) {
        const int idx = i * 512 + t;
        const int n = idx >> 2, c = idx & 3;
        ((float4*)slab)[idx] = *(const float4*)(fb + (size_t)n * HD_ + hd0 + c * 4);
    }
    __syncthreads();

    const int hd = t & 15, nb = t >> 4;
    __half* ob = g_outf + (size_t)b * N_ * D_ + h * HD_ + hd0 + hd;
    for (int ni = 0; ni < 64; ni++) {
        const int n = ni * 32 + nb;
        const float* gp = g_gains + ((size_t)bh * N_ + n) * S_;

        float acc = D4_3 * slab[n * 16 + hd];
#pragma unroll
        for (int j = 0; j < S_; j++) {
            const int d = 1 << j;
            const float g = __ldg(&gp[j]);
            const int s3 = n - 3 * d, s2 = n - 2 * d, s1 = n - d;
            if (s3 >= 0) acc = fmaf(g * D4_0, slab[s3 * 16 + hd], acc);
            if (s2 >= 0) acc = fmaf(g * D4_1, slab[s2 * 16 + hd], acc);
            if (s1 >= 0) acc = fmaf(g * D4_2, slab[s1 * 16 + hd], acc);
        }
        ob[(size_t)n * D_] = __float2half(acc);
    }
}

// -------- stage: head coupling + gate; emits fp16 hi/lo of G ------------------
__global__ __launch_bounds__(256)
void couple_gate_kernel(const float* __restrict__ fc)
{
    __shared__ float sf[D_];
    __shared__ float cp[H_][H_];

    const int bn = blockIdx.x;
    const int tid = threadIdx.x;

    const __half2* orow = (const __half2*)(g_outf + (size_t)bn * D_);
#pragma unroll
    for (int r = 0; r < 2; r++) {
        const int i = tid + r * 256;           // 512 half2
        const float2 f = __half22float2(orow[i]);
        sf[2 * i] = f.x; sf[2 * i + 1] = f.y;
    }
    if (tid < H_) {
        float row[H_];
        float mx = -1e30f;
#pragma unroll
        for (int j = 0; j < H_; j++) { row[j] = fc[tid * H_ + j]; mx = fmaxf(mx, row[j]); }
        float sum = 0.f;
#pragma unroll
        for (int j = 0; j < H_; j++) { row[j] = __expf(row[j] - mx); sum += row[j]; }
        const float inv = 1.f / sum;
#pragma unroll
        for (int j = 0; j < H_; j++) cp[tid][j] = row[j] * inv;
    }
    __syncthreads();

    const size_t grow = (size_t)bn * D_;
#pragma unroll
    for (int r = 0; r < 4; r++) {
        const int idx = tid + r * 256;
        const int i = idx >> 6, hd = idx & 63;
        float acc = 0.f;
#pragma unroll
        for (int j = 0; j < H_; j++) acc = fmaf(cp[i][j], sf[j * HD_ + hd], acc);
        const float v = acc * __half2float(g_gate[grow + idx]);
        const __half h = __float2half(v);
        g_Ghi[grow + idx] = h;
        g_Glo[grow + idx] = __float2half(v - __half2float(h));
    }
}

// ------------------------------- launch --------------------------------------
extern "C" void kernel_launch(void* const* d_in, const int* in_sizes, int n_in,
                              void* d_out, int out_size)
{
    const float* x    = (const float*)d_in[0];
    const float* Wqkv = (const float*)d_in[1];
    const float* bqkv = (const float*)d_in[2];
    const float* Wo   = (const float*)d_in[3];
    const float* bo   = (const float*)d_in[4];
    const float* Wg   = (const float*)d_in[5];
    const float* bg   = (const float*)d_in[6];
    const float* scale_gain = (const float*)d_in[7];
    const float* Wqs  = (const float*)d_in[8];
    const float* fc   = (const float*)d_in[9];
    float* out = (float*)d_out;

    float *p_logits, *p_kmag;
    __half *p_gate, *p_xhi, *p_xlo, *p_Ghi, *p_Glo, *p_Wkvhi, *p_Wohi, *p_Weff;
    cudaGetSymbolAddress((void**)&p_gate, g_gate);
    cudaGetSymbolAddress((void**)&p_logits, g_logits);
    cudaGetSymbolAddress((void**)&p_kmag, g_kmag);
    cudaGetSymbolAddress((void**)&p_xhi, g_xhi);   cudaGetSymbolAddress((void**)&p_xlo, g_xlo);
    cudaGetSymbolAddress((void**)&p_Ghi, g_Ghi);   cudaGetSymbolAddress((void**)&p_Glo, g_Glo);
    cudaGetSymbolAddress((void**)&p_Wkvhi, g_Wkvhi);
    cudaGetSymbolAddress((void**)&p_Wohi, g_Wohi);
    cudaGetSymbolAddress((void**)&p_Weff, g_Weffhi);
    __half* p_Wghi;
    cudaGetSymbolAddress((void**)&p_Wghi, g_Wghi);

    cudaFuncSetAttribute(gemm_1pass_combo,  cudaFuncAttributeMaxDynamicSharedMemorySize, NSTAGE * 2 * TILEB);
    cudaFuncSetAttribute(gemm_2pass<false>, cudaFuncAttributeMaxDynamicSharedMemorySize, NSTAGE * 3 * TILEB);
    cudaFuncSetAttribute(gemm_2pass<true>,  cudaFuncAttributeMaxDynamicSharedMemorySize, NSTAGE * 3 * TILEB);
    cudaFuncSetAttribute(conv_kernel2, cudaFuncAttributeMaxDynamicSharedMemorySize, CONV_SMEM);

    // 0) fused splits + Weff precompute
    fused_split_kernel<<<(SPLIT_TOT + 255) / 256, 256>>>(
        (const float4*)x, (const float4*)(Wqkv + (size_t)D_ * D_),
        (const float4*)Wg, (const float4*)Wo);
    {
        dim3 wgrid(D_ / 256, 256);
        weff_kernel<<<wgrid, 256>>>(Wqkv, Wqs, p_Weff);
    }

    // 1) combined 1-pass: kmag | gate | logits
    {
        dim3 grid(18, M_ / GBM);
        gemm_1pass_combo<<<grid, 256, NSTAGE * 2 * TILEB>>>(
            p_xhi, p_Wkvhi, p_Wghi, p_Weff,
            bqkv + D_, bg, p_kmag, p_gate, p_logits);
    }
    // 2) gains softmax
    gains_kernel<<<M_ * H_ / 256, 256>>>(p_logits, scale_gain);

    // 3) v-GEMM -> field = (x@Wv^T + bv) * kmag, written in [bh][n][hd]
    {
        dim3 grid(D_ / GBN, M_ / GBM);
        gemm_2pass<true><<<grid, 256, NSTAGE * 3 * TILEB>>>(
            p_xhi, p_xlo, p_Wkvhi + (size_t)D_ * D_,
            bqkv + 2 * D_, nullptr, p_kmag, 0, D_);
    }
    // 4) multiscale causal conv -> outf [b][n][D] (fp16)
    {
        dim3 grid(HD_ / 16, B_ * H_);
        conv_kernel2<<<grid, 512, CONV_SMEM>>>();
    }
    // 5) head coupling + gate (emits fp16 hi/lo of G)
    couple_gate_kernel<<<B_ * N_, 256>>>(fc);

    // 6) out = G @ Wo^T + bo   (2-pass, G compensated)
    {
        dim3 grid(D_ / GBN, M_ / GBM);
        gemm_2pass<false><<<grid, 256, NSTAGE * 3 * TILEB>>>(
            p_Ghi, p_Glo, p_Wohi, bo, out, nullptr, D_, D_);
    }
}

// round 8
// speedup vs baseline: 5.1530x; 1.2493x over previous
#include <cuda_runtime.h>
#include <cuda_fp16.h>
#include <math.h>
#include <stdint.h>

// Problem dims (fixed by the reference)
#define B_    4
#define N_    2048
#define D_    1024
#define H_    16
#define HD_   64
#define S_    11
#define M_    (B_ * N_)   // 8192

#define D4_0 0.4829629131445341f
#define D4_1 0.8365163037378079f
#define D4_2 0.2241438680420134f
#define D4_3 (-0.1294095225512604f)

// ---------------- scratch (static device globals; no allocation) -------------
__device__ __align__(256) __half g_gate[M_ * D_];
__device__ __align__(256) float g_logits[M_ * 256];     // h*11+s cols (176 used)
__device__ __align__(256) float g_kmag[M_ * H_];        // [m][h]
__device__ __align__(256) float g_vfield[B_ * H_ * N_ * HD_];  // raw v, [bh][n][hd]
__device__ __align__(256) float g_gains[B_ * H_ * N_ * S_];    // [bh][n][s]
__device__ __align__(256) __half g_outf [M_ * D_];      // [b][n][h*64+hd]

__device__ __align__(256) __half g_xhi[M_ * D_];
__device__ __align__(256) __half g_Ghi[M_ * D_];
__device__ __align__(256) __half g_Wkvhi[2 * D_ * D_];  // Wk, Wv hi
__device__ __align__(256) __half g_Wghi[D_ * D_];
__device__ __align__(256) __half g_Wohi[D_ * D_];
__device__ __align__(256) __half g_Weffhi[256 * D_];    // rows 176..255 zero

// ============================ PTX helpers ====================================
__device__ __forceinline__ uint32_t smem_u32(const void* p) {
    uint32_t a;
    asm("{ .reg .u64 t; cvta.to.shared.u64 t, %1; cvt.u32.u64 %0, t; }" : "=r"(a) : "l"(p));
    return a;
}

#define CP_ASYNC_16(sp, gp) \
    asm volatile("cp.async.cg.shared.global [%0], [%1], 16;" :: "r"(sp), "l"(gp) : "memory")
#define CP_COMMIT() asm volatile("cp.async.commit_group;" ::: "memory")
#define CP_WAIT(n)  asm volatile("cp.async.wait_group %0;" :: "n"(n) : "memory")

#define LDSM4(r0, r1, r2, r3, addr) \
    asm volatile("ldmatrix.sync.aligned.m8n8.x4.shared.b16 {%0,%1,%2,%3}, [%4];" \
        : "=r"(r0), "=r"(r1), "=r"(r2), "=r"(r3) : "r"(addr))
#define LDSM2(r0, r1, addr) \
    asm volatile("ldmatrix.sync.aligned.m8n8.x2.shared.b16 {%0,%1}, [%2];" \
        : "=r"(r0), "=r"(r1) : "r"(addr))

#define MMA16816(d, a, b) \
    asm volatile("mma.sync.aligned.m16n8k16.row.col.f32.f16.f16.f32 " \
        "{%0,%1,%2,%3}, {%4,%5,%6,%7}, {%8,%9}, {%0,%1,%2,%3};" \
        : "+f"((d)[0]), "+f"((d)[1]), "+f"((d)[2]), "+f"((d)[3]) \
        : "r"((a)[0]), "r"((a)[1]), "r"((a)[2]), "r"((a)[3]), "r"((b)[0]), "r"((b)[1]))

// ======================= fp16 tensor-core GEMM building blocks ===============
#define GBM 128
#define GBN 128
#define GBK 32
#define NSTAGE 4
#define ROWB   80
#define TILEB  (128 * ROWB)
#define STAGEB (2 * TILEB)
#define GEMM_SMEM (NSTAGE * STAGEB)

// ---- mega combo 1-pass GEMM: kmag | gate | logits | v in one launch ---------
// bx 0..7:   k -> reduce ||k|| per head -> g_kmag
// bx 8..15:  gate = sigmoid(x@Wg^T+bg) -> g_gate (fp16)
// bx 16..17: logits = x@Weff^T -> g_logits
// bx 18..25: v = x@Wv^T+bv -> g_vfield [bh][n][hd] (fp32, no kmag)
__global__ __launch_bounds__(256, 1)
void gemm_combo(const __half* __restrict__ xhi,
                const __half* __restrict__ Wk,
                const __half* __restrict__ Wg,
                const __half* __restrict__ Weff,
                const __half* __restrict__ Wv,
                const float* __restrict__ bk,
                const float* __restrict__ bg,
                const float* __restrict__ bv,
                float* __restrict__ Ckmag, __half* __restrict__ Cgate,
                float* __restrict__ Clog)
{
    constexpr int K = D_;
    extern __shared__ char smx[];
    const uint32_t sbase = smem_u32(smx);
    const int t = threadIdx.x;
    const int wid = t >> 5, lane = t & 31;
    const int wm = wid & 3, wn = wid >> 2;
    const int m0 = blockIdx.y * GBM;
    const int bx = blockIdx.x;

    const __half* Bp;
    if (bx < 8)       Bp = Wk   + (size_t)bx * 128 * K;
    else if (bx < 16) Bp = Wg   + (size_t)(bx - 8) * 128 * K;
    else if (bx < 18) Bp = Weff + (size_t)(bx - 16) * 128 * K;
    else              Bp = Wv   + (size_t)(bx - 18) * 128 * K;

    const int KITERS = K / GBK;

    float acc[2][8][4];
#pragma unroll
    for (int mi = 0; mi < 2; mi++)
#pragma unroll
        for (int ni = 0; ni < 8; ni++)
#pragma unroll
            for (int v = 0; v < 4; v++) acc[mi][ni][v] = 0.f;

    auto load_stage = [&](int stage, int kk) {
        const uint32_t sb = sbase + stage * STAGEB;
        const int r = t >> 2, c = t & 3;
#pragma unroll
        for (int j = 0; j < 4; j++) {
            const int tile = j >> 1;
            const int row  = ((j & 1) << 6) + r;
            const __half* g = (tile == 0) ? xhi : Bp;
            const int grow  = (tile == 0) ? (m0 + row) : row;
            CP_ASYNC_16(sb + tile * TILEB + row * ROWB + c * 16,
                        g + (size_t)grow * K + kk + c * 8);
        }
        CP_COMMIT();
    };

#pragma unroll
    for (int s = 0; s < NSTAGE - 1; s++) load_stage(s, s * GBK);

    const uint32_t a_off = (wm * 32 + (lane & 15)) * ROWB + (lane >> 4) * 16;
    const uint32_t b_off = (wn * 64 + (lane & 7)) * ROWB + ((lane >> 3) & 1) * 16;

    for (int it = 0; it < KITERS; it++) {
        CP_WAIT(NSTAGE - 2);
        __syncthreads();
        const int kload = it + NSTAGE - 1;
        if (kload < KITERS) load_stage(kload % NSTAGE, kload * GBK);

        const uint32_t st = sbase + (it % NSTAGE) * STAGEB;
#pragma unroll
        for (int ks = 0; ks < 2; ks++) {
            const uint32_t kb = ks * 32;
            uint32_t ah[2][4], bh[8][2];
#pragma unroll
            for (int mi = 0; mi < 2; mi++) {
                const uint32_t ar = st + a_off + mi * (16 * ROWB) + kb;
                LDSM4(ah[mi][0], ah[mi][1], ah[mi][2], ah[mi][3], ar);
            }
#pragma unroll
            for (int ni = 0; ni < 8; ni++) {
                const uint32_t br = st + TILEB + b_off + ni * (8 * ROWB) + kb;
                LDSM2(bh[ni][0], bh[ni][1], br);
            }
#pragma unroll
            for (int mi = 0; mi < 2; mi++)
#pragma unroll
                for (int ni = 0; ni < 8; ni++)
                    MMA16816(acc[mi][ni], ah[mi], bh[ni]);
        }
    }

    const int mrow = m0 + wm * 32 + (lane >> 2);
    const int ncl  = wn * 64 + (lane & 3) * 2;

    if (bx < 8) {
        // ||k||: this block's 128 cols = heads 2bx, 2bx+1; wn selects head
        float rs[2][2] = {{0.f, 0.f}, {0.f, 0.f}};
#pragma unroll
        for (int mi = 0; mi < 2; mi++)
#pragma unroll
            for (int ni = 0; ni < 8; ni++) {
                const int cl = bx * 128 + ncl + ni * 8;
                const float b0 = __ldg(&bk[cl]);
                const float b1 = __ldg(&bk[cl + 1]);
                const float v0 = acc[mi][ni][0] + b0, v1 = acc[mi][ni][1] + b1;
                const float v2 = acc[mi][ni][2] + b0, v3 = acc[mi][ni][3] + b1;
                rs[mi][0] += v0 * v0 + v1 * v1;
                rs[mi][1] += v2 * v2 + v3 * v3;
            }
#pragma unroll
        for (int mi = 0; mi < 2; mi++)
#pragma unroll
            for (int hf = 0; hf < 2; hf++) {
                rs[mi][hf] += __shfl_xor_sync(0xffffffffu, rs[mi][hf], 1);
                rs[mi][hf] += __shfl_xor_sync(0xffffffffu, rs[mi][hf], 2);
            }
        if ((lane & 3) == 0) {
            const int head = bx * 2 + wn;
#pragma unroll
            for (int mi = 0; mi < 2; mi++) {
                const int r0 = mrow + mi * 16;
                Ckmag[(size_t)r0 * H_ + head]       = sqrtf(rs[mi][0]);
                Ckmag[(size_t)(r0 + 8) * H_ + head] = sqrtf(rs[mi][1]);
            }
        }
    } else if (bx < 16) {
#pragma unroll
        for (int mi = 0; mi < 2; mi++)
#pragma unroll
            for (int ni = 0; ni < 8; ni++) {
                const int cl = (bx - 8) * 128 + ncl + ni * 8;
                const float b0 = __ldg(&bg[cl]);
                const float b1 = __ldg(&bg[cl + 1]);
                float v0 = acc[mi][ni][0] + b0, v1 = acc[mi][ni][1] + b1;
                float v2 = acc[mi][ni][2] + b0, v3 = acc[mi][ni][3] + b1;
                v0 = 1.f / (1.f + __expf(-v0)); v1 = 1.f / (1.f + __expf(-v1));
                v2 = 1.f / (1.f + __expf(-v2)); v3 = 1.f / (1.f + __expf(-v3));
                const int r0 = mrow + mi * 16;
                *(__half2*)(Cgate + (size_t)r0 * D_ + cl)       = __floats2half2_rn(v0, v1);
                *(__half2*)(Cgate + (size_t)(r0 + 8) * D_ + cl) = __floats2half2_rn(v2, v3);
            }
    } else if (bx < 18) {
#pragma unroll
        for (int mi = 0; mi < 2; mi++)
#pragma unroll
            for (int ni = 0; ni < 8; ni++) {
                const int cl = (bx - 16) * 128 + ncl + ni * 8;
                const int r0 = mrow + mi * 16;
                *(float2*)(Clog + (size_t)r0 * 256 + cl) =
                    make_float2(acc[mi][ni][0], acc[mi][ni][1]);
                *(float2*)(Clog + (size_t)(r0 + 8) * 256 + cl) =
                    make_float2(acc[mi][ni][2], acc[mi][ni][3]);
            }
    } else {
        // v region: scatter raw v (+bias) into g_vfield [bh][n][hd]
        const int head = (bx - 18) * 2 + wn;
        const int hdb  = (lane & 3) * 2;
#pragma unroll
        for (int mi = 0; mi < 2; mi++) {
            const int r0 = mrow + mi * 16;
            const int r1 = r0 + 8;
            float* f0 = g_vfield + (((size_t)((r0 >> 11) * H_ + head) * N_ + (r0 & (N_ - 1))) * HD_);
            float* f1 = g_vfield + (((size_t)((r1 >> 11) * H_ + head) * N_ + (r1 & (N_ - 1))) * HD_);
#pragma unroll
            for (int ni = 0; ni < 8; ni++) {
                const int hd = hdb + ni * 8;
                const int cg = head * 64 + hd;
                const float b0 = __ldg(&bv[cg]);
                const float b1 = __ldg(&bv[cg + 1]);
                *(float2*)(f0 + hd) = make_float2(acc[mi][ni][0] + b0, acc[mi][ni][1] + b1);
                *(float2*)(f1 + hd) = make_float2(acc[mi][ni][2] + b0, acc[mi][ni][3] + b1);
            }
        }
    }
}

// ---- out GEMM (1-pass): out = Ghi @ Wohi^T + bo ------------------------------
__global__ __launch_bounds__(256, 1)
void gemm_out(const __half* __restrict__ Ahi, const __half* __restrict__ Bhi,
              const float* __restrict__ bias, float* __restrict__ C)
{
    constexpr int K = D_;
    extern __shared__ char smx[];
    const uint32_t sbase = smem_u32(smx);
    const int t = threadIdx.x;
    const int wid = t >> 5, lane = t & 31;
    const int wm = wid & 3, wn = wid >> 2;
    const int m0 = blockIdx.y * GBM;
    const int n0 = blockIdx.x * GBN;
    const int KITERS = K / GBK;

    float acc[2][8][4];
#pragma unroll
    for (int mi = 0; mi < 2; mi++)
#pragma unroll
        for (int ni = 0; ni < 8; ni++)
#pragma unroll
            for (int v = 0; v < 4; v++) acc[mi][ni][v] = 0.f;

    auto load_stage = [&](int stage, int kk) {
        const uint32_t sb = sbase + stage * STAGEB;
        const int r = t >> 2, c = t & 3;
#pragma unroll
        for (int j = 0; j < 4; j++) {
            const int tile = j >> 1;
            const int row  = ((j & 1) << 6) + r;
            const __half* g = (tile == 0) ? Ahi : Bhi;
            const int grow  = (tile == 0) ? (m0 + row) : (n0 + row);
            CP_ASYNC_16(sb + tile * TILEB + row * ROWB + c * 16,
                        g + (size_t)grow * K + kk + c * 8);
        }
        CP_COMMIT();
    };

#pragma unroll
    for (int s = 0; s < NSTAGE - 1; s++) load_stage(s, s * GBK);

    const uint32_t a_off = (wm * 32 + (lane & 15)) * ROWB + (lane >> 4) * 16;
    const uint32_t b_off = (wn * 64 + (lane & 7)) * ROWB + ((lane >> 3) & 1) * 16;

    for (int it = 0; it < KITERS; it++) {
        CP_WAIT(NSTAGE - 2);
        __syncthreads();
        const int kload = it + NSTAGE - 1;
        if (kload < KITERS) load_stage(kload % NSTAGE, kload * GBK);

        const uint32_t st = sbase + (it % NSTAGE) * STAGEB;
#pragma unroll
        for (int ks = 0; ks < 2; ks++) {
            const uint32_t kb = ks * 32;
            uint32_t ah[2][4], bh[8][2];
#pragma unroll
            for (int mi = 0; mi < 2; mi++) {
                const uint32_t ar = st + a_off + mi * (16 * ROWB) + kb;
                LDSM4(ah[mi][0], ah[mi][1], ah[mi][2], ah[mi][3], ar);
            }
#pragma unroll
            for (int ni = 0; ni < 8; ni++) {
                const uint32_t br = st + TILEB + b_off + ni * (8 * ROWB) + kb;
                LDSM2(bh[ni][0], bh[ni][1], br);
            }
#pragma unroll
            for (int mi = 0; mi < 2; mi++)
#pragma unroll
                for (int ni = 0; ni < 8; ni++)
                    MMA16816(acc[mi][ni], ah[mi], bh[ni]);
        }
    }

    const int mrow = m0 + wm * 32 + (lane >> 2);
    const int ncol = n0 + wn * 64 + (lane & 3) * 2;
#pragma unroll
    for (int mi = 0; mi < 2; mi++)
#pragma unroll
        for (int ni = 0; ni < 8; ni++) {
            const int cbase = ncol + ni * 8;
            const float b0 = __ldg(&bias[cbase]);
            const float b1 = __ldg(&bias[cbase + 1]);
            const int r0 = mrow + mi * 16;
            *(float2*)(C + (size_t)r0 * D_ + cbase) =
                make_float2(acc[mi][ni][0] + b0, acc[mi][ni][1] + b1);
            *(float2*)(C + (size_t)(r0 + 8) * D_ + cbase) =
                make_float2(acc[mi][ni][2] + b0, acc[mi][ni][3] + b1);
        }
}

// ---------------- fused hi-only splits: x, Wkv, Wg, Wo ------------------------
#define SPLIT_X   (M_ * D_ / 4)
#define SPLIT_KV  (2 * D_ * D_ / 4)
#define SPLIT_W   (D_ * D_ / 4)
#define SPLIT_TOT (SPLIT_X + SPLIT_KV + 2 * SPLIT_W)

__global__ __launch_bounds__(256)
void fused_split_kernel(const float4* __restrict__ x, const float4* __restrict__ Wkv,
                        const float4* __restrict__ Wg, const float4* __restrict__ Wo)
{
    const int i = blockIdx.x * blockDim.x + threadIdx.x;
    if (i >= SPLIT_TOT) return;
    const float4* src;
    __half2* dst;
    int j;
    if (i < SPLIT_X)                          { j = i;                          src = x;   dst = (__half2*)g_xhi; }
    else if (i < SPLIT_X + SPLIT_KV)          { j = i - SPLIT_X;                src = Wkv; dst = (__half2*)g_Wkvhi; }
    else if (i < SPLIT_X + SPLIT_KV + SPLIT_W){ j = i - SPLIT_X - SPLIT_KV;     src = Wg;  dst = (__half2*)g_Wghi; }
    else                                      { j = i - SPLIT_X - SPLIT_KV - SPLIT_W; src = Wo; dst = (__half2*)g_Wohi; }
    const float4 v = src[j];
    dst[2 * j]     = __halves2half2(__float2half(v.x), __float2half(v.y));
    dst[2 * j + 1] = __halves2half2(__float2half(v.z), __float2half(v.w));
}

// ---------------- Weff = Wqs @ Wq (per head), fp32 -> fp16 --------------------
__global__ __launch_bounds__(256)
void weff_kernel(const float* __restrict__ Wqkv, const float* __restrict__ Wqs,
                 __half* __restrict__ Weff)
{
    const int r = blockIdx.y;
    const int k = blockIdx.x * 256 + threadIdx.x;
    float acc = 0.f;
    if (r < 176) {
        const int h = r / 11, s = r % 11;
        const float* wq = Wqkv + (size_t)(h * 64) * D_ + k;
        const float* ws = Wqs + s * HD_;
#pragma unroll 16
        for (int d = 0; d < 64; d++)
            acc = fmaf(__ldg(&ws[d]), __ldg(&wq[(size_t)d * D_]), acc);
    }
    Weff[(size_t)r * D_ + k] = __float2half(acc);
}

// -------- gains: softmax over S logits per (m, h); coalesced writes ----------
__global__ __launch_bounds__(256)
void gains_kernel(const float* __restrict__ logits,
                  const float* __restrict__ scale_gain)
{
    const int t = threadIdx.x;
    const int h  = t >> 4;                        // 0..15
    const int ml = t & 15;
    const int m  = blockIdx.x * 16 + ml;
    const float* lp = logits + (size_t)m * 256 + h * S_;

    float l[S_];
    float mx = -1e30f;
#pragma unroll
    for (int s = 0; s < S_; s++) {
        l[s] = __ldg(&lp[s]) + __ldg(&scale_gain[s * H_ + h]);
        mx = fmaxf(mx, l[s]);
    }
    float sum = 0.f;
#pragma unroll
    for (int s = 0; s < S_; s++) { l[s] = __expf(l[s] - mx); sum += l[s]; }
    const float inv = 1.f / sum;

    float* gp = g_gains + ((size_t)((m >> 11) * H_ + h) * N_ + (m & (N_ - 1))) * S_;
#pragma unroll
    for (int s = 0; s < S_; s++) gp[s] = l[s] * inv;
}

// -------- stage: causal multiscale dilated D4 conv (smem-slab) ----------------
// slab load applies kmag (field = v * ||k||); outf written [b][n][D] fp16
#define CONV_SMEM (N_ * 16 * 4)   // 131072 B

__global__ __launch_bounds__(512)
void conv_kernel2()
{
    extern __shared__ float slab[];          // [2048][16]
    const int bh  = blockIdx.y;
    const int hd0 = blockIdx.x * 16;
    const int t   = threadIdx.x;
    const int b   = bh >> 4, h = bh & 15;

    const float* fb = g_vfield + (size_t)bh * N_ * HD_;
#pragma unroll
    for (int i = 0; i < 16; i++) {
        const int idx = i * 512 + t;
        const int n = idx >> 2, c = idx & 3;
        float4 v = *(const float4*)(fb + (size_t)n * HD_ + hd0 + c * 4);
        const float km = __ldg(&g_kmag[((size_t)(b * N_ + n)) * H_ + h]);
        v.x *= km; v.y *= km; v.z *= km; v.w *= km;
        ((float4*)slab)[idx] = v;
    }
    __syncthreads();

    const int hd = t & 15, nb = t >> 4;
    __half* ob = g_outf + (size_t)b * N_ * D_ + h * HD_ + hd0 + hd;
    for (int ni = 0; ni < 64; ni++) {
        const int n = ni * 32 + nb;
        const float* gp = g_gains + ((size_t)bh * N_ + n) * S_;

        float acc = D4_3 * slab[n * 16 + hd];
#pragma unroll
        for (int j = 0; j < S_; j++) {
            const int d = 1 << j;
            const float g = __ldg(&gp[j]);
            const int s3 = n - 3 * d, s2 = n - 2 * d, s1 = n - d;
            if (s3 >= 0) acc = fmaf(g * D4_0, slab[s3 * 16 + hd], acc);
            if (s2 >= 0) acc = fmaf(g * D4_1, slab[s2 * 16 + hd], acc);
            if (s1 >= 0) acc = fmaf(g * D4_2, slab[s1 * 16 + hd], acc);
        }
        ob[(size_t)n * D_] = __float2half(acc);
    }
}

// -------- stage: head coupling + gate; emits fp16 G (hi only) -----------------
__global__ __launch_bounds__(256)
void couple_gate_kernel(const float* __restrict__ fc)
{
    __shared__ float sf[D_];
    __shared__ float cp[H_][H_];

    const int bn = blockIdx.x;
    const int tid = threadIdx.x;

    const __half2* orow = (const __half2*)(g_outf + (size_t)bn * D_);
#pragma unroll
    for (int r = 0; r < 2; r++) {
        const int i = tid + r * 256;
        const float2 f = __half22float2(orow[i]);
        sf[2 * i] = f.x; sf[2 * i + 1] = f.y;
    }
    if (tid < H_) {
        float row[H_];
        float mx = -1e30f;
#pragma unroll
        for (int j = 0; j < H_; j++) { row[j] = fc[tid * H_ + j]; mx = fmaxf(mx, row[j]); }
        float sum = 0.f;
#pragma unroll
        for (int j = 0; j < H_; j++) { row[j] = __expf(row[j] - mx); sum += row[j]; }
        const float inv = 1.f / sum;
#pragma unroll
        for (int j = 0; j < H_; j++) cp[tid][j] = row[j] * inv;
    }
    __syncthreads();

    const size_t grow = (size_t)bn * D_;
#pragma unroll
    for (int r = 0; r < 4; r++) {
        const int idx = tid + r * 256;
        const int i = idx >> 6, hd = idx & 63;
        float acc = 0.f;
#pragma unroll
        for (int j = 0; j < H_; j++) acc = fmaf(cp[i][j], sf[j * HD_ + hd], acc);
        g_Ghi[grow + idx] = __float2half(acc * __half2float(g_gate[grow + idx]));
    }
}

// ------------------------------- launch --------------------------------------
extern "C" void kernel_launch(void* const* d_in, const int* in_sizes, int n_in,
                              void* d_out, int out_size)
{
    const float* x    = (const float*)d_in[0];
    const float* Wqkv = (const float*)d_in[1];
    const float* bqkv = (const float*)d_in[2];
    const float* Wo   = (const float*)d_in[3];
    const float* bo   = (const float*)d_in[4];
    const float* Wg   = (const float*)d_in[5];
    const float* bg   = (const float*)d_in[6];
    const float* scale_gain = (const float*)d_in[7];
    const float* Wqs  = (const float*)d_in[8];
    const float* fc   = (const float*)d_in[9];
    float* out = (float*)d_out;

    float *p_logits, *p_kmag;
    __half *p_gate, *p_xhi, *p_Ghi, *p_Wkvhi, *p_Wghi, *p_Wohi, *p_Weff;
    cudaGetSymbolAddress((void**)&p_gate, g_gate);
    cudaGetSymbolAddress((void**)&p_logits, g_logits);
    cudaGetSymbolAddress((void**)&p_kmag, g_kmag);
    cudaGetSymbolAddress((void**)&p_xhi, g_xhi);
    cudaGetSymbolAddress((void**)&p_Ghi, g_Ghi);
    cudaGetSymbolAddress((void**)&p_Wkvhi, g_Wkvhi);
    cudaGetSymbolAddress((void**)&p_Wghi, g_Wghi);
    cudaGetSymbolAddress((void**)&p_Wohi, g_Wohi);
    cudaGetSymbolAddress((void**)&p_Weff, g_Weffhi);

    cudaFuncSetAttribute(gemm_combo, cudaFuncAttributeMaxDynamicSharedMemorySize, GEMM_SMEM);
    cudaFuncSetAttribute(gemm_out,   cudaFuncAttributeMaxDynamicSharedMemorySize, GEMM_SMEM);
    cudaFuncSetAttribute(conv_kernel2, cudaFuncAttributeMaxDynamicSharedMemorySize, CONV_SMEM);

    // 0) fused hi-only splits + Weff precompute
    fused_split_kernel<<<(SPLIT_TOT + 255) / 256, 256>>>(
        (const float4*)x, (const float4*)(Wqkv + (size_t)D_ * D_),
        (const float4*)Wg, (const float4*)Wo);
    {
        dim3 wgrid(D_ / 256, 256);
        weff_kernel<<<wgrid, 256>>>(Wqkv, Wqs, p_Weff);
    }

    // 1) mega combo: kmag | gate | logits | v  (all 1-pass, one launch)
    {
        dim3 grid(26, M_ / GBM);
        gemm_combo<<<grid, 256, GEMM_SMEM>>>(
            p_xhi, p_Wkvhi, p_Wghi, p_Weff, p_Wkvhi + (size_t)D_ * D_,
            bqkv + D_, bg, bqkv + 2 * D_,
            p_kmag, p_gate, p_logits);
    }
    // 2) gains softmax
    gains_kernel<<<M_ / 16, 256>>>(p_logits, scale_gain);

    // 3) multiscale causal conv (kmag applied at slab load) -> outf fp16
    {
        dim3 grid(HD_ / 16, B_ * H_);
        conv_kernel2<<<grid, 512, CONV_SMEM>>>();
    }
    // 4) head coupling + gate -> Ghi (fp16)
    couple_gate_kernel<<<B_ * N_, 256>>>(fc);

    // 5) out = Ghi @ Wohi^T + bo   (1-pass)
    {
        dim3 grid(D_ / GBN, M_ / GBM);
        gemm_out<<<grid, 256, GEMM_SMEM>>>(p_Ghi, p_Wohi, bo, out);
    }
}